// round 4
// baseline (speedup 1.0000x reference)
#include <cuda_runtime.h>
#include <math.h>
#include <stdint.h>

#define DMODEL 1024
#define NH     16
#define DEPTH  64
#define BATCH  2
#define SEQ    2048
#define MROWS  (BATCH*SEQ)   // 4096
#define NT     (SEQ/32)      // 64 kv chunks

// Scratch (allocation-free rule: __device__ globals)
__device__ float g_Qh[BATCH*NH*SEQ*DEPTH];
__device__ float g_Kh[BATCH*NH*SEQ*DEPTH];
__device__ float g_Vh[BATCH*NH*SEQ*DEPTH];
__device__ float g_Oc[MROWS*DMODEL];

__device__ __forceinline__ float to_tf32(float x) {
    float r;
    asm("cvt.rna.tf32.f32 %0, %1;" : "=f"(r) : "f"(x));
    return r;
}
__device__ __forceinline__ float4 cvt4(float4 v) {
    return make_float4(to_tf32(v.x), to_tf32(v.y), to_tf32(v.z), to_tf32(v.w));
}

__device__ __forceinline__ void mma8(float c[4], const uint32_t a[4], const uint32_t b[2]) {
    asm volatile(
        "mma.sync.aligned.m16n8k8.row.col.f32.tf32.tf32.f32 "
        "{%0,%1,%2,%3},{%4,%5,%6,%7},{%8,%9},{%0,%1,%2,%3};\n"
        : "+f"(c[0]), "+f"(c[1]), "+f"(c[2]), "+f"(c[3])
        : "r"(a[0]), "r"(a[1]), "r"(a[2]), "r"(a[3]), "r"(b[0]), "r"(b[1]));
}

// ---------------------------------------------------------------------------
// C = A[4096,1024] @ W[1024,1024]^T + bias, tf32 tensor-core GEMM.
// 128x128 block tile, BK=16, 8 warps x (64x32). 2-stage smem double buffer,
// one __syncthreads per BK. QKV=true fuses the 3 projections via blockIdx.z.
// ---------------------------------------------------------------------------
template<bool SPLIT, bool QKV>
__global__ __launch_bounds__(256, 2)
void gemm_tc(const float* __restrict__ A0, const float* __restrict__ W0,
             const float* __restrict__ b0, float* __restrict__ C0,
             const float* __restrict__ A1, const float* __restrict__ W1,
             const float* __restrict__ b1, float* __restrict__ C1,
             const float* __restrict__ A2, const float* __restrict__ W2,
             const float* __restrict__ b2, float* __restrict__ C2)
{
    __shared__ float As[2][128][20];
    __shared__ float Ws[2][128][20];

    const float* A    = A0;
    const float* W    = W0;
    const float* bias = b0;
    float*       C    = C0;
    if (QKV) {
        const int z = blockIdx.z;
        if (z == 1) { A = A1; W = W1; bias = b1; C = C1; }
        else if (z == 2) { A = A2; W = W2; bias = b2; C = C2; }
    }

    const int tid  = threadIdx.x;
    const int lane = tid & 31, wid = tid >> 5;
    const int wm   = wid >> 2, wn = wid & 3;
    const int g    = lane >> 2, t = lane & 3;
    const int bm   = blockIdx.y * 128, bn = blockIdx.x * 128;

    const int lr = tid >> 1;          // 0..127
    const int lc = (tid & 1) * 8;     // 0 or 8
    const float* Ap = A + (size_t)(bm + lr) * DMODEL + lc;
    const float* Wp = W + (size_t)(bn + lr) * DMODEL + lc;

    // stage 0: k=0
    {
        float4 a0 = *(const float4*)(Ap),     a1 = *(const float4*)(Ap + 4);
        float4 w0 = *(const float4*)(Wp),     w1 = *(const float4*)(Wp + 4);
        *(float4*)&As[0][lr][lc]   = cvt4(a0);
        *(float4*)&As[0][lr][lc+4] = cvt4(a1);
        *(float4*)&Ws[0][lr][lc]   = cvt4(w0);
        *(float4*)&Ws[0][lr][lc+4] = cvt4(w1);
    }
    // prefetch k=16 into regs
    float4 pa0 = *(const float4*)(Ap + 16), pa1 = *(const float4*)(Ap + 20);
    float4 pw0 = *(const float4*)(Wp + 16), pw1 = *(const float4*)(Wp + 20);
    __syncthreads();

    float acc[4][4][4] = {};
    int buf = 0;

    for (int k0 = 0; k0 < DMODEL; k0 += 16) {
        const int kn = k0 + 16;
        if (kn < DMODEL) {
            // commit prefetched kn -> other stage (safe: other stage was drained
            // before the sync that ended the previous iteration)
            *(float4*)&As[buf^1][lr][lc]   = cvt4(pa0);
            *(float4*)&As[buf^1][lr][lc+4] = cvt4(pa1);
            *(float4*)&Ws[buf^1][lr][lc]   = cvt4(pw0);
            *(float4*)&Ws[buf^1][lr][lc+4] = cvt4(pw1);
            const int kf = kn + 16;
            if (kf < DMODEL) {
                pa0 = *(const float4*)(Ap + kf); pa1 = *(const float4*)(Ap + kf + 4);
                pw0 = *(const float4*)(Wp + kf); pw1 = *(const float4*)(Wp + kf + 4);
            }
        }

#pragma unroll
        for (int ks = 0; ks < 2; ++ks) {
            const int kb = ks * 8;
            uint32_t af[4][4], bf[4][2];
#pragma unroll
            for (int mt = 0; mt < 4; ++mt) {
                const int r = wm*64 + mt*16 + g;
                af[mt][0] = __float_as_uint(As[buf][r  ][kb + t]);
                af[mt][1] = __float_as_uint(As[buf][r+8][kb + t]);
                af[mt][2] = __float_as_uint(As[buf][r  ][kb + t + 4]);
                af[mt][3] = __float_as_uint(As[buf][r+8][kb + t + 4]);
            }
#pragma unroll
            for (int nt = 0; nt < 4; ++nt) {
                const int n = wn*32 + nt*8 + g;
                bf[nt][0] = __float_as_uint(Ws[buf][n][kb + t]);
                bf[nt][1] = __float_as_uint(Ws[buf][n][kb + t + 4]);
            }
#pragma unroll
            for (int mt = 0; mt < 4; ++mt)
#pragma unroll
                for (int nt = 0; nt < 4; ++nt)
                    mma8(acc[mt][nt], af[mt], bf[nt]);
        }
        __syncthreads();
        buf ^= 1;
    }

    // epilogue
#pragma unroll
    for (int mt = 0; mt < 4; ++mt) {
        const int r0 = bm + wm*64 + mt*16 + g;
#pragma unroll
        for (int nt = 0; nt < 4; ++nt) {
            const int c0 = bn + wn*32 + nt*8 + t*2;
            const float bb0 = bias[c0], bb1 = bias[c0 + 1];
            const float v00 = acc[mt][nt][0] + bb0, v01 = acc[mt][nt][1] + bb1;
            const float v10 = acc[mt][nt][2] + bb0, v11 = acc[mt][nt][3] + bb1;
            if (SPLIT) {
                const int bb = r0 >> 11;
                const int s  = r0 & (SEQ - 1);
                const int h  = c0 >> 6;
                const int d  = c0 & 63;
                float* p0 = C + (((size_t)(bb*NH + h))*SEQ + s    )*DEPTH + d;
                float* p1 = C + (((size_t)(bb*NH + h))*SEQ + s + 8)*DEPTH + d;
                *(float2*)p0 = make_float2(v00, v01);
                *(float2*)p1 = make_float2(v10, v11);
            } else {
                *(float2*)(C + (size_t)r0      * DMODEL + c0) = make_float2(v00, v01);
                *(float2*)(C + (size_t)(r0+8)  * DMODEL + c0) = make_float2(v10, v11);
            }
        }
    }
}

// ---------------------------------------------------------------------------
// Flash attention, tf32 tensor cores.
// Block = 128 threads (4 warps), q-tile 64, kv-chunk 32.
// Q fragments held in registers for the whole block.
// K/V double-buffered in smem with register prefetch -> 1 sync per chunk.
// Smem: Ks[2][32][68] + Vt[2][64][36] + Ps[64][36] = 44.0 KB.
// ---------------------------------------------------------------------------
__global__ __launch_bounds__(128, 4)
void attn_tc(const float* __restrict__ Qh, const float* __restrict__ Kh,
             const float* __restrict__ Vh, const float* __restrict__ mask,
             float* __restrict__ Oc)
{
    __shared__ float Ks[2][32][68];
    __shared__ float Vt[2][64][36];
    __shared__ float Ps[64][36];

    const int tid  = threadIdx.x;
    const int lane = tid & 31, w = tid >> 5;
    const int g    = lane >> 2, t = lane & 3;
    const int bh   = blockIdx.x;         // b*NH + h
    const int qt   = blockIdx.y;
    const int b    = bh >> 4, h = bh & 15;

    // --- Q fragments -> registers (one-time) ---
    const float* Qb    = Qh + ((size_t)bh * SEQ + qt*64) * DEPTH;
    const float* qrow0 = Qb + (w*16 + g    ) * DEPTH;
    const float* qrow1 = Qb + (w*16 + g + 8) * DEPTH;
    uint32_t qf[8][4];
#pragma unroll
    for (int kb8 = 0; kb8 < 8; ++kb8) {
        qf[kb8][0] = __float_as_uint(to_tf32(__ldg(qrow0 + kb8*8 + t)));
        qf[kb8][1] = __float_as_uint(to_tf32(__ldg(qrow1 + kb8*8 + t)));
        qf[kb8][2] = __float_as_uint(to_tf32(__ldg(qrow0 + kb8*8 + t + 4)));
        qf[kb8][3] = __float_as_uint(to_tf32(__ldg(qrow1 + kb8*8 + t + 4)));
    }

    const float* Kb0 = Kh + (size_t)bh * SEQ * DEPTH;
    const float* Vb0 = Vh + (size_t)bh * SEQ * DEPTH;
    const float* Mb  = mask + ((size_t)b * SEQ + qt*64) * SEQ;
    const int pr = w*16 + g;

    // per-thread K/V load mapping
    const int kr  = tid >> 4;           // K rows handled: kr, kr+8, kr+16, kr+24
    const int kc4 = (tid & 15) * 4;
    const int vc  = tid & 31;           // V col (seq pos within chunk)
    const int vd4 = (tid >> 5) * 4;     // V depth base: vd4, +16, +32, +48

    float4 pk[4], pv[4];
    // chunk 0 -> regs -> smem stage 0
#pragma unroll
    for (int j = 0; j < 4; ++j) {
        pk[j] = *(const float4*)(Kb0 + (size_t)(kr + j*8)*DEPTH + kc4);
        pv[j] = *(const float4*)(Vb0 + (size_t)vc*DEPTH + vd4 + j*16);
    }
#pragma unroll
    for (int j = 0; j < 4; ++j) {
        *(float4*)&Ks[0][kr + j*8][kc4] = cvt4(pk[j]);
        const int d = vd4 + j*16;
        Vt[0][d+0][vc] = to_tf32(pv[j].x); Vt[0][d+1][vc] = to_tf32(pv[j].y);
        Vt[0][d+2][vc] = to_tf32(pv[j].z); Vt[0][d+3][vc] = to_tf32(pv[j].w);
    }
    // prefetch chunk 1
#pragma unroll
    for (int j = 0; j < 4; ++j) {
        pk[j] = *(const float4*)(Kb0 + (size_t)(32 + kr + j*8)*DEPTH + kc4);
        pv[j] = *(const float4*)(Vb0 + (size_t)(32 + vc)*DEPTH + vd4 + j*16);
    }
    __syncthreads();

    float oacc[8][4] = {};
    float m0 = -INFINITY, m1 = -INFINITY, l0 = 0.f, l1 = 0.f;
    int buf = 0;

    for (int kt = 0; kt < NT; ++kt) {
        if (kt + 1 < NT) {
            // commit prefetched chunk kt+1 to the other stage (drained last iter)
#pragma unroll
            for (int j = 0; j < 4; ++j) {
                *(float4*)&Ks[buf^1][kr + j*8][kc4] = cvt4(pk[j]);
                const int d = vd4 + j*16;
                Vt[buf^1][d+0][vc] = to_tf32(pv[j].x); Vt[buf^1][d+1][vc] = to_tf32(pv[j].y);
                Vt[buf^1][d+2][vc] = to_tf32(pv[j].z); Vt[buf^1][d+3][vc] = to_tf32(pv[j].w);
            }
            if (kt + 2 < NT) {
                const int base = (kt + 2) * 32;
#pragma unroll
                for (int j = 0; j < 4; ++j) {
                    pk[j] = *(const float4*)(Kb0 + (size_t)(base + kr + j*8)*DEPTH + kc4);
                    pv[j] = *(const float4*)(Vb0 + (size_t)(base + vc)*DEPTH + vd4 + j*16);
                }
            }
        }

        // S = Q @ K^T  (16x32 per warp)
        float sacc[4][4] = {};
#pragma unroll
        for (int ks = 0; ks < 8; ++ks) {
            const int kb = ks * 8;
#pragma unroll
            for (int nt = 0; nt < 4; ++nt) {
                uint32_t bf[2];
                bf[0] = __float_as_uint(Ks[buf][nt*8 + g][kb + t]);
                bf[1] = __float_as_uint(Ks[buf][nt*8 + g][kb + t + 4]);
                mma8(sacc[nt], qf[ks], bf);
            }
        }

        // scale + additive mask
#pragma unroll
        for (int nt = 0; nt < 4; ++nt) {
            const int c0 = kt*32 + nt*8 + t*2;
            float2 mlo = *(const float2*)(Mb + (size_t)(w*16 + g    )*SEQ + c0);
            float2 mhi = *(const float2*)(Mb + (size_t)(w*16 + g + 8)*SEQ + c0);
            sacc[nt][0] = fmaf(mlo.x, -1e9f, sacc[nt][0]*0.125f);
            sacc[nt][1] = fmaf(mlo.y, -1e9f, sacc[nt][1]*0.125f);
            sacc[nt][2] = fmaf(mhi.x, -1e9f, sacc[nt][2]*0.125f);
            sacc[nt][3] = fmaf(mhi.y, -1e9f, sacc[nt][3]*0.125f);
        }

        // online softmax (2 rows per thread, quad reduction over lane%4)
        float rm0 = -INFINITY, rm1 = -INFINITY;
#pragma unroll
        for (int nt = 0; nt < 4; ++nt) {
            rm0 = fmaxf(rm0, fmaxf(sacc[nt][0], sacc[nt][1]));
            rm1 = fmaxf(rm1, fmaxf(sacc[nt][2], sacc[nt][3]));
        }
        rm0 = fmaxf(rm0, __shfl_xor_sync(0xffffffffu, rm0, 1));
        rm0 = fmaxf(rm0, __shfl_xor_sync(0xffffffffu, rm0, 2));
        rm1 = fmaxf(rm1, __shfl_xor_sync(0xffffffffu, rm1, 1));
        rm1 = fmaxf(rm1, __shfl_xor_sync(0xffffffffu, rm1, 2));

        const float mn0 = fmaxf(m0, rm0), mn1 = fmaxf(m1, rm1);
        const float a0  = __expf(m0 - mn0), a1 = __expf(m1 - mn1);
        m0 = mn0; m1 = mn1;

        float sum0 = 0.f, sum1 = 0.f;
#pragma unroll
        for (int nt = 0; nt < 4; ++nt) {
            sacc[nt][0] = __expf(sacc[nt][0] - mn0); sum0 += sacc[nt][0];
            sacc[nt][1] = __expf(sacc[nt][1] - mn0); sum0 += sacc[nt][1];
            sacc[nt][2] = __expf(sacc[nt][2] - mn1); sum1 += sacc[nt][2];
            sacc[nt][3] = __expf(sacc[nt][3] - mn1); sum1 += sacc[nt][3];
        }
        sum0 += __shfl_xor_sync(0xffffffffu, sum0, 1);
        sum0 += __shfl_xor_sync(0xffffffffu, sum0, 2);
        sum1 += __shfl_xor_sync(0xffffffffu, sum1, 1);
        sum1 += __shfl_xor_sync(0xffffffffu, sum1, 2);
        l0 = l0*a0 + sum0;
        l1 = l1*a1 + sum1;
#pragma unroll
        for (int nt = 0; nt < 8; ++nt) {
            oacc[nt][0] *= a0; oacc[nt][1] *= a0;
            oacc[nt][2] *= a1; oacc[nt][3] *= a1;
        }

        // P -> smem (warp-private rows, tf32-rounded)
#pragma unroll
        for (int nt = 0; nt < 4; ++nt) {
            *(float2*)&Ps[pr    ][nt*8 + t*2] = make_float2(to_tf32(sacc[nt][0]), to_tf32(sacc[nt][1]));
            *(float2*)&Ps[pr + 8][nt*8 + t*2] = make_float2(to_tf32(sacc[nt][2]), to_tf32(sacc[nt][3]));
        }
        __syncwarp();

        // O += P @ V   (16x64 per warp, K=32)
#pragma unroll
        for (int ks = 0; ks < 4; ++ks) {
            const int kb = ks * 8;
            uint32_t af[4];
            af[0] = __float_as_uint(Ps[pr    ][kb + t]);
            af[1] = __float_as_uint(Ps[pr + 8][kb + t]);
            af[2] = __float_as_uint(Ps[pr    ][kb + t + 4]);
            af[3] = __float_as_uint(Ps[pr + 8][kb + t + 4]);
#pragma unroll
            for (int nt = 0; nt < 8; ++nt) {
                uint32_t bf[2];
                bf[0] = __float_as_uint(Vt[buf][nt*8 + g][kb + t]);
                bf[1] = __float_as_uint(Vt[buf][nt*8 + g][kb + t + 4]);
                mma8(oacc[nt], af, bf);
            }
        }
        __syncthreads();
        buf ^= 1;
    }

    // epilogue: normalize + concat heads -> Oc[b*S + s][h*64 + d]
    const float inv0 = 1.f / l0, inv1 = 1.f / l1;
    const size_t row0 = (size_t)b*SEQ + qt*64 + w*16 + g;
#pragma unroll
    for (int nt = 0; nt < 8; ++nt) {
        const int c = h*64 + nt*8 + t*2;
        *(float2*)(Oc + row0     * DMODEL + c) = make_float2(oacc[nt][0]*inv0, oacc[nt][1]*inv0);
        *(float2*)(Oc + (row0+8) * DMODEL + c) = make_float2(oacc[nt][2]*inv1, oacc[nt][3]*inv1);
    }
}

// ---------------------------------------------------------------------------
extern "C" void kernel_launch(void* const* d_in, const int* in_sizes, int n_in,
                              void* d_out, int out_size)
{
    const float* v    = (const float*)d_in[0];
    const float* k    = (const float*)d_in[1];
    const float* q    = (const float*)d_in[2];
    const float* mask = (const float*)d_in[3];
    const float* wq   = (const float*)d_in[4];
    const float* bq   = (const float*)d_in[5];
    const float* wk   = (const float*)d_in[6];
    const float* bk   = (const float*)d_in[7];
    const float* wv   = (const float*)d_in[8];
    const float* bv   = (const float*)d_in[9];
    const float* wo   = (const float*)d_in[10];
    const float* bo   = (const float*)d_in[11];
    float* out = (float*)d_out;

    float *Qh, *Kh, *Vh, *Oc;
    cudaGetSymbolAddress((void**)&Qh, g_Qh);
    cudaGetSymbolAddress((void**)&Kh, g_Kh);
    cudaGetSymbolAddress((void**)&Vh, g_Vh);
    cudaGetSymbolAddress((void**)&Oc, g_Oc);

    // fused Q/K/V projections: one launch, blockIdx.z selects the GEMM
    dim3 gqkv(DMODEL/128, MROWS/128, 3);  // (8, 32, 3)
    gemm_tc<true, true><<<gqkv, 256>>>(q, wq, bq, Qh,
                                       k, wk, bk, Kh,
                                       v, wv, bv, Vh);

    dim3 ga(BATCH*NH, SEQ/64);            // (32, 32)
    attn_tc<<<ga, 128>>>(Qh, Kh, Vh, mask, Oc);

    dim3 gg(DMODEL/128, MROWS/128);       // (8, 32)
    gemm_tc<false, false><<<gg, 256>>>(Oc, wo, bo, out,
                                       nullptr, nullptr, nullptr, nullptr,
                                       nullptr, nullptr, nullptr, nullptr);
}

// round 9
// speedup vs baseline: 1.5097x; 1.5097x over previous
#include <cuda_runtime.h>
#include <math.h>
#include <stdint.h>

#define DMODEL 1024
#define NH     16
#define DEPTH  64
#define BATCH  2
#define SEQ    2048
#define MROWS  (BATCH*SEQ)   // 4096
#define NT     (SEQ/32)      // 64 kv chunks

// Scratch (allocation-free rule: __device__ globals)
__device__ float g_Qh[BATCH*NH*SEQ*DEPTH];
__device__ float g_Kh[BATCH*NH*SEQ*DEPTH];
__device__ float g_Vh[BATCH*NH*SEQ*DEPTH];
__device__ float g_Oc[MROWS*DMODEL];

__device__ __forceinline__ float to_tf32(float x) {
    float r;
    asm("cvt.rna.tf32.f32 %0, %1;" : "=f"(r) : "f"(x));
    return r;
}
__device__ __forceinline__ float4 cvt4(float4 v) {
    return make_float4(to_tf32(v.x), to_tf32(v.y), to_tf32(v.z), to_tf32(v.w));
}

__device__ __forceinline__ void mma8(float c[4], const uint32_t a[4], const uint32_t b[2]) {
    asm volatile(
        "mma.sync.aligned.m16n8k8.row.col.f32.tf32.tf32.f32 "
        "{%0,%1,%2,%3},{%4,%5,%6,%7},{%8,%9},{%0,%1,%2,%3};\n"
        : "+f"(c[0]), "+f"(c[1]), "+f"(c[2]), "+f"(c[3])
        : "r"(a[0]), "r"(a[1]), "r"(a[2]), "r"(a[3]), "r"(b[0]), "r"(b[1]));
}

// ---------------------------------------------------------------------------
// C = A[4096,1024] @ W[1024,1024]^T + bias, tf32 tensor-core GEMM.
// Round-2 proven version: 128x128 tile, BK=16, single smem buffer (20KB),
// register prefetch, no min-blocks clamp. QKV=true fuses the 3 projections
// via blockIdx.z (only structural change vs round 2).
// ---------------------------------------------------------------------------
template<bool SPLIT, bool QKV>
__global__ __launch_bounds__(256)
void gemm_tc(const float* __restrict__ A0, const float* __restrict__ W0,
             const float* __restrict__ b0, float* __restrict__ C0,
             const float* __restrict__ A1, const float* __restrict__ W1,
             const float* __restrict__ b1, float* __restrict__ C1,
             const float* __restrict__ A2, const float* __restrict__ W2,
             const float* __restrict__ b2, float* __restrict__ C2)
{
    __shared__ float As[128][20];
    __shared__ float Ws[128][20];

    const float* A    = A0;
    const float* W    = W0;
    const float* bias = b0;
    float*       C    = C0;
    if (QKV) {
        const int z = blockIdx.z;
        if (z == 1) { A = A1; W = W1; bias = b1; C = C1; }
        else if (z == 2) { A = A2; W = W2; bias = b2; C = C2; }
    }

    const int tid  = threadIdx.x;
    const int lane = tid & 31, wid = tid >> 5;
    const int wm   = wid >> 2, wn = wid & 3;
    const int g    = lane >> 2, t = lane & 3;
    const int bm   = blockIdx.y * 128, bn = blockIdx.x * 128;

    const int lr = tid >> 1;          // 0..127
    const int lc = (tid & 1) * 8;     // 0 or 8
    const float* Ap = A + (size_t)(bm + lr) * DMODEL + lc;
    const float* Wp = W + (size_t)(bn + lr) * DMODEL + lc;

    float4 pa0 = *(const float4*)(Ap),     pa1 = *(const float4*)(Ap + 4);
    float4 pw0 = *(const float4*)(Wp),     pw1 = *(const float4*)(Wp + 4);

    float acc[4][4][4] = {};

    for (int k0 = 0;;) {
        // commit prefetched tile (tf32-rounded) to smem
        *(float4*)&As[lr][lc]   = cvt4(pa0);
        *(float4*)&As[lr][lc+4] = cvt4(pa1);
        *(float4*)&Ws[lr][lc]   = cvt4(pw0);
        *(float4*)&Ws[lr][lc+4] = cvt4(pw1);
        __syncthreads();

        const int kn = k0 + 16;
        if (kn < DMODEL) {
            pa0 = *(const float4*)(Ap + kn); pa1 = *(const float4*)(Ap + kn + 4);
            pw0 = *(const float4*)(Wp + kn); pw1 = *(const float4*)(Wp + kn + 4);
        }

#pragma unroll
        for (int ks = 0; ks < 2; ++ks) {
            const int kb = ks * 8;
            uint32_t af[4][4], bf[4][2];
#pragma unroll
            for (int mt = 0; mt < 4; ++mt) {
                const int r = wm*64 + mt*16 + g;
                af[mt][0] = __float_as_uint(As[r  ][kb + t]);
                af[mt][1] = __float_as_uint(As[r+8][kb + t]);
                af[mt][2] = __float_as_uint(As[r  ][kb + t + 4]);
                af[mt][3] = __float_as_uint(As[r+8][kb + t + 4]);
            }
#pragma unroll
            for (int nt = 0; nt < 4; ++nt) {
                const int n = wn*32 + nt*8 + g;
                bf[nt][0] = __float_as_uint(Ws[n][kb + t]);
                bf[nt][1] = __float_as_uint(Ws[n][kb + t + 4]);
            }
#pragma unroll
            for (int mt = 0; mt < 4; ++mt)
#pragma unroll
                for (int nt = 0; nt < 4; ++nt)
                    mma8(acc[mt][nt], af[mt], bf[nt]);
        }

        k0 = kn;
        if (k0 >= DMODEL) break;
        __syncthreads();
    }

    // epilogue
#pragma unroll
    for (int mt = 0; mt < 4; ++mt) {
        const int r0 = bm + wm*64 + mt*16 + g;
#pragma unroll
        for (int nt = 0; nt < 4; ++nt) {
            const int c0 = bn + wn*32 + nt*8 + t*2;
            const float bb0 = bias[c0], bb1 = bias[c0 + 1];
            const float v00 = acc[mt][nt][0] + bb0, v01 = acc[mt][nt][1] + bb1;
            const float v10 = acc[mt][nt][2] + bb0, v11 = acc[mt][nt][3] + bb1;
            if (SPLIT) {
                const int bb = r0 >> 11;
                const int s  = r0 & (SEQ - 1);
                const int h  = c0 >> 6;
                const int d  = c0 & 63;
                float* p0 = C + (((size_t)(bb*NH + h))*SEQ + s    )*DEPTH + d;
                float* p1 = C + (((size_t)(bb*NH + h))*SEQ + s + 8)*DEPTH + d;
                *(float2*)p0 = make_float2(v00, v01);
                *(float2*)p1 = make_float2(v10, v11);
            } else {
                *(float2*)(C + (size_t)r0      * DMODEL + c0) = make_float2(v00, v01);
                *(float2*)(C + (size_t)(r0+8)  * DMODEL + c0) = make_float2(v10, v11);
            }
        }
    }
}

// ---------------------------------------------------------------------------
// Flash attention, tf32 tensor cores (round-3 version — confirmed faster).
// Block = 128 threads (4 warps), q-tile 64, kv-chunk 32.
// Q fragments held in registers for the whole block.
// K/V double-buffered in smem with register prefetch -> 1 sync per chunk.
// Smem: Ks[2][32][68] + Vt[2][64][36] + Ps[64][36] = 44.0 KB.
// ---------------------------------------------------------------------------
__global__ __launch_bounds__(128, 4)
void attn_tc(const float* __restrict__ Qh, const float* __restrict__ Kh,
             const float* __restrict__ Vh, const float* __restrict__ mask,
             float* __restrict__ Oc)
{
    __shared__ float Ks[2][32][68];
    __shared__ float Vt[2][64][36];
    __shared__ float Ps[64][36];

    const int tid  = threadIdx.x;
    const int lane = tid & 31, w = tid >> 5;
    const int g    = lane >> 2, t = lane & 3;
    const int bh   = blockIdx.x;         // b*NH + h
    const int qt   = blockIdx.y;
    const int b    = bh >> 4, h = bh & 15;

    // --- Q fragments -> registers (one-time) ---
    const float* Qb    = Qh + ((size_t)bh * SEQ + qt*64) * DEPTH;
    const float* qrow0 = Qb + (w*16 + g    ) * DEPTH;
    const float* qrow1 = Qb + (w*16 + g + 8) * DEPTH;
    uint32_t qf[8][4];
#pragma unroll
    for (int kb8 = 0; kb8 < 8; ++kb8) {
        qf[kb8][0] = __float_as_uint(to_tf32(__ldg(qrow0 + kb8*8 + t)));
        qf[kb8][1] = __float_as_uint(to_tf32(__ldg(qrow1 + kb8*8 + t)));
        qf[kb8][2] = __float_as_uint(to_tf32(__ldg(qrow0 + kb8*8 + t + 4)));
        qf[kb8][3] = __float_as_uint(to_tf32(__ldg(qrow1 + kb8*8 + t + 4)));
    }

    const float* Kb0 = Kh + (size_t)bh * SEQ * DEPTH;
    const float* Vb0 = Vh + (size_t)bh * SEQ * DEPTH;
    const float* Mb  = mask + ((size_t)b * SEQ + qt*64) * SEQ;
    const int pr = w*16 + g;

    // per-thread K/V load mapping
    const int kr  = tid >> 4;           // K rows handled: kr, kr+8, kr+16, kr+24
    const int kc4 = (tid & 15) * 4;
    const int vc  = tid & 31;           // V col (seq pos within chunk)
    const int vd4 = (tid >> 5) * 4;     // V depth base: vd4, +16, +32, +48

    float4 pk[4], pv[4];
    // chunk 0 -> regs -> smem stage 0
#pragma unroll
    for (int j = 0; j < 4; ++j) {
        pk[j] = *(const float4*)(Kb0 + (size_t)(kr + j*8)*DEPTH + kc4);
        pv[j] = *(const float4*)(Vb0 + (size_t)vc*DEPTH + vd4 + j*16);
    }
#pragma unroll
    for (int j = 0; j < 4; ++j) {
        *(float4*)&Ks[0][kr + j*8][kc4] = cvt4(pk[j]);
        const int d = vd4 + j*16;
        Vt[0][d+0][vc] = to_tf32(pv[j].x); Vt[0][d+1][vc] = to_tf32(pv[j].y);
        Vt[0][d+2][vc] = to_tf32(pv[j].z); Vt[0][d+3][vc] = to_tf32(pv[j].w);
    }
    // prefetch chunk 1
#pragma unroll
    for (int j = 0; j < 4; ++j) {
        pk[j] = *(const float4*)(Kb0 + (size_t)(32 + kr + j*8)*DEPTH + kc4);
        pv[j] = *(const float4*)(Vb0 + (size_t)(32 + vc)*DEPTH + vd4 + j*16);
    }
    __syncthreads();

    float oacc[8][4] = {};
    float m0 = -INFINITY, m1 = -INFINITY, l0 = 0.f, l1 = 0.f;
    int buf = 0;

    for (int kt = 0; kt < NT; ++kt) {
        if (kt + 1 < NT) {
            // commit prefetched chunk kt+1 to the other stage (drained last iter)
#pragma unroll
            for (int j = 0; j < 4; ++j) {
                *(float4*)&Ks[buf^1][kr + j*8][kc4] = cvt4(pk[j]);
                const int d = vd4 + j*16;
                Vt[buf^1][d+0][vc] = to_tf32(pv[j].x); Vt[buf^1][d+1][vc] = to_tf32(pv[j].y);
                Vt[buf^1][d+2][vc] = to_tf32(pv[j].z); Vt[buf^1][d+3][vc] = to_tf32(pv[j].w);
            }
            if (kt + 2 < NT) {
                const int base = (kt + 2) * 32;
#pragma unroll
                for (int j = 0; j < 4; ++j) {
                    pk[j] = *(const float4*)(Kb0 + (size_t)(base + kr + j*8)*DEPTH + kc4);
                    pv[j] = *(const float4*)(Vb0 + (size_t)(base + vc)*DEPTH + vd4 + j*16);
                }
            }
        }

        // S = Q @ K^T  (16x32 per warp)
        float sacc[4][4] = {};
#pragma unroll
        for (int ks = 0; ks < 8; ++ks) {
            const int kb = ks * 8;
#pragma unroll
            for (int nt = 0; nt < 4; ++nt) {
                uint32_t bf[2];
                bf[0] = __float_as_uint(Ks[buf][nt*8 + g][kb + t]);
                bf[1] = __float_as_uint(Ks[buf][nt*8 + g][kb + t + 4]);
                mma8(sacc[nt], qf[ks], bf);
            }
        }

        // scale + additive mask
#pragma unroll
        for (int nt = 0; nt < 4; ++nt) {
            const int c0 = kt*32 + nt*8 + t*2;
            float2 mlo = *(const float2*)(Mb + (size_t)(w*16 + g    )*SEQ + c0);
            float2 mhi = *(const float2*)(Mb + (size_t)(w*16 + g + 8)*SEQ + c0);
            sacc[nt][0] = fmaf(mlo.x, -1e9f, sacc[nt][0]*0.125f);
            sacc[nt][1] = fmaf(mlo.y, -1e9f, sacc[nt][1]*0.125f);
            sacc[nt][2] = fmaf(mhi.x, -1e9f, sacc[nt][2]*0.125f);
            sacc[nt][3] = fmaf(mhi.y, -1e9f, sacc[nt][3]*0.125f);
        }

        // online softmax (2 rows per thread, quad reduction over lane%4)
        float rm0 = -INFINITY, rm1 = -INFINITY;
#pragma unroll
        for (int nt = 0; nt < 4; ++nt) {
            rm0 = fmaxf(rm0, fmaxf(sacc[nt][0], sacc[nt][1]));
            rm1 = fmaxf(rm1, fmaxf(sacc[nt][2], sacc[nt][3]));
        }
        rm0 = fmaxf(rm0, __shfl_xor_sync(0xffffffffu, rm0, 1));
        rm0 = fmaxf(rm0, __shfl_xor_sync(0xffffffffu, rm0, 2));
        rm1 = fmaxf(rm1, __shfl_xor_sync(0xffffffffu, rm1, 1));
        rm1 = fmaxf(rm1, __shfl_xor_sync(0xffffffffu, rm1, 2));

        const float mn0 = fmaxf(m0, rm0), mn1 = fmaxf(m1, rm1);
        const float a0  = __expf(m0 - mn0), a1 = __expf(m1 - mn1);
        m0 = mn0; m1 = mn1;

        float sum0 = 0.f, sum1 = 0.f;
#pragma unroll
        for (int nt = 0; nt < 4; ++nt) {
            sacc[nt][0] = __expf(sacc[nt][0] - mn0); sum0 += sacc[nt][0];
            sacc[nt][1] = __expf(sacc[nt][1] - mn0); sum0 += sacc[nt][1];
            sacc[nt][2] = __expf(sacc[nt][2] - mn1); sum1 += sacc[nt][2];
            sacc[nt][3] = __expf(sacc[nt][3] - mn1); sum1 += sacc[nt][3];
        }
        sum0 += __shfl_xor_sync(0xffffffffu, sum0, 1);
        sum0 += __shfl_xor_sync(0xffffffffu, sum0, 2);
        sum1 += __shfl_xor_sync(0xffffffffu, sum1, 1);
        sum1 += __shfl_xor_sync(0xffffffffu, sum1, 2);
        l0 = l0*a0 + sum0;
        l1 = l1*a1 + sum1;
#pragma unroll
        for (int nt = 0; nt < 8; ++nt) {
            oacc[nt][0] *= a0; oacc[nt][1] *= a0;
            oacc[nt][2] *= a1; oacc[nt][3] *= a1;
        }

        // P -> smem (warp-private rows, tf32-rounded)
#pragma unroll
        for (int nt = 0; nt < 4; ++nt) {
            *(float2*)&Ps[pr    ][nt*8 + t*2] = make_float2(to_tf32(sacc[nt][0]), to_tf32(sacc[nt][1]));
            *(float2*)&Ps[pr + 8][nt*8 + t*2] = make_float2(to_tf32(sacc[nt][2]), to_tf32(sacc[nt][3]));
        }
        __syncwarp();

        // O += P @ V   (16x64 per warp, K=32)
#pragma unroll
        for (int ks = 0; ks < 4; ++ks) {
            const int kb = ks * 8;
            uint32_t af[4];
            af[0] = __float_as_uint(Ps[pr    ][kb + t]);
            af[1] = __float_as_uint(Ps[pr + 8][kb + t]);
            af[2] = __float_as_uint(Ps[pr    ][kb + t + 4]);
            af[3] = __float_as_uint(Ps[pr + 8][kb + t + 4]);
#pragma unroll
            for (int nt = 0; nt < 8; ++nt) {
                uint32_t bf[2];
                bf[0] = __float_as_uint(Vt[buf][nt*8 + g][kb + t]);
                bf[1] = __float_as_uint(Vt[buf][nt*8 + g][kb + t + 4]);
                mma8(oacc[nt], af, bf);
            }
        }
        __syncthreads();
        buf ^= 1;
    }

    // epilogue: normalize + concat heads -> Oc[b*S + s][h*64 + d]
    const float inv0 = 1.f / l0, inv1 = 1.f / l1;
    const size_t row0 = (size_t)b*SEQ + qt*64 + w*16 + g;
#pragma unroll
    for (int nt = 0; nt < 8; ++nt) {
        const int c = h*64 + nt*8 + t*2;
        *(float2*)(Oc + row0     * DMODEL + c) = make_float2(oacc[nt][0]*inv0, oacc[nt][1]*inv0);
        *(float2*)(Oc + (row0+8) * DMODEL + c) = make_float2(oacc[nt][2]*inv1, oacc[nt][3]*inv1);
    }
}

// ---------------------------------------------------------------------------
extern "C" void kernel_launch(void* const* d_in, const int* in_sizes, int n_in,
                              void* d_out, int out_size)
{
    const float* v    = (const float*)d_in[0];
    const float* k    = (const float*)d_in[1];
    const float* q    = (const float*)d_in[2];
    const float* mask = (const float*)d_in[3];
    const float* wq   = (const float*)d_in[4];
    const float* bq   = (const float*)d_in[5];
    const float* wk   = (const float*)d_in[6];
    const float* bk   = (const float*)d_in[7];
    const float* wv   = (const float*)d_in[8];
    const float* bv   = (const float*)d_in[9];
    const float* wo   = (const float*)d_in[10];
    const float* bo   = (const float*)d_in[11];
    float* out = (float*)d_out;

    float *Qh, *Kh, *Vh, *Oc;
    cudaGetSymbolAddress((void**)&Qh, g_Qh);
    cudaGetSymbolAddress((void**)&Kh, g_Kh);
    cudaGetSymbolAddress((void**)&Vh, g_Vh);
    cudaGetSymbolAddress((void**)&Oc, g_Oc);

    // fused Q/K/V projections: one launch, blockIdx.z selects the GEMM
    dim3 gqkv(DMODEL/128, MROWS/128, 3);  // (8, 32, 3)
    gemm_tc<true, true><<<gqkv, 256>>>(q, wq, bq, Qh,
                                       k, wk, bk, Kh,
                                       v, wv, bv, Vh);

    dim3 ga(BATCH*NH, SEQ/64);            // (32, 32)
    attn_tc<<<ga, 128>>>(Qh, Kh, Vh, mask, Oc);

    dim3 gg(DMODEL/128, MROWS/128);       // (8, 32)
    gemm_tc<false, false><<<gg, 256>>>(Oc, wo, bo, out,
                                       nullptr, nullptr, nullptr, nullptr,
                                       nullptr, nullptr, nullptr, nullptr);
}

// round 11
// speedup vs baseline: 1.7663x; 1.1700x over previous
#include <cuda_runtime.h>
#include <math.h>
#include <stdint.h>

#define DMODEL 1024
#define NH     16
#define DEPTH  64
#define BATCH  2
#define SEQ    2048
#define MROWS  (BATCH*SEQ)   // 4096
#define NT     (SEQ/32)      // 64 kv chunks

// Scratch (allocation-free rule: __device__ globals)
__device__ float g_Qh[BATCH*NH*SEQ*DEPTH];
__device__ float g_Kh[BATCH*NH*SEQ*DEPTH];
__device__ float g_Vh[BATCH*NH*SEQ*DEPTH];
__device__ float g_Oc[MROWS*DMODEL];

__device__ __forceinline__ float to_tf32(float x) {
    float r;
    asm("cvt.rna.tf32.f32 %0, %1;" : "=f"(r) : "f"(x));
    return r;
}
__device__ __forceinline__ float4 cvt4(float4 v) {
    return make_float4(to_tf32(v.x), to_tf32(v.y), to_tf32(v.z), to_tf32(v.w));
}

__device__ __forceinline__ void mma8(float c[4], const uint32_t a[4], const uint32_t b[2]) {
    asm volatile(
        "mma.sync.aligned.m16n8k8.row.col.f32.tf32.tf32.f32 "
        "{%0,%1,%2,%3},{%4,%5,%6,%7},{%8,%9},{%0,%1,%2,%3};\n"
        : "+f"(c[0]), "+f"(c[1]), "+f"(c[2]), "+f"(c[3])
        : "r"(a[0]), "r"(a[1]), "r"(a[2]), "r"(a[3]), "r"(b[0]), "r"(b[1]));
}

// ldmatrix x4: four 8x4-tf32 tiles in one instruction.
__device__ __forceinline__ void ldsm4(uint32_t* r, uint32_t addr) {
    asm volatile("ldmatrix.sync.aligned.m8n8.x4.shared.b16 {%0,%1,%2,%3}, [%4];"
                 : "=r"(r[0]), "=r"(r[1]), "=r"(r[2]), "=r"(r[3]) : "r"(addr));
}

// ---------------------------------------------------------------------------
// C = A[4096,1024] @ W[1024,1024]^T + bias, tf32 tensor-core GEMM.
// 128x128 tile, BK=16, single smem buffer, register prefetch.
// Fragments loaded via ldmatrix.x4. QKV=true fuses the 3 projections.
// ---------------------------------------------------------------------------
template<bool SPLIT, bool QKV>
__global__ __launch_bounds__(256)
void gemm_tc(const float* __restrict__ A0, const float* __restrict__ W0,
             const float* __restrict__ b0, float* __restrict__ C0,
             const float* __restrict__ A1, const float* __restrict__ W1,
             const float* __restrict__ b1, float* __restrict__ C1,
             const float* __restrict__ A2, const float* __restrict__ W2,
             const float* __restrict__ b2, float* __restrict__ C2)
{
    __shared__ float As[128][20];
    __shared__ float Ws[128][20];

    const float* A    = A0;
    const float* W    = W0;
    const float* bias = b0;
    float*       C    = C0;
    if (QKV) {
        const int z = blockIdx.z;
        if (z == 1) { A = A1; W = W1; bias = b1; C = C1; }
        else if (z == 2) { A = A2; W = W2; bias = b2; C = C2; }
    }

    const int tid  = threadIdx.x;
    const int lane = tid & 31, wid = tid >> 5;
    const int wm   = wid >> 2, wn = wid & 3;
    const int g    = lane >> 2, t = lane & 3;
    const int bm   = blockIdx.y * 128, bn = blockIdx.x * 128;

    // ldmatrix per-lane address components
    const int arow = lane & 15;                            // A-frag row offset
    const int acol = (lane >> 4) * 4;                      // A-frag col offset (0|4)
    const int brow = ((lane >> 4) << 3) + (lane & 7);      // B-frag row offset
    const int bcol = ((lane >> 3) & 1) * 4;                // B-frag col offset (0|4)

    const uint32_t As_b = (uint32_t)__cvta_generic_to_shared(&As[0][0]);
    const uint32_t Ws_b = (uint32_t)__cvta_generic_to_shared(&Ws[0][0]);

    const int lr = tid >> 1;          // 0..127
    const int lc = (tid & 1) * 8;     // 0 or 8
    const float* Ap = A + (size_t)(bm + lr) * DMODEL + lc;
    const float* Wp = W + (size_t)(bn + lr) * DMODEL + lc;

    float4 pa0 = *(const float4*)(Ap),     pa1 = *(const float4*)(Ap + 4);
    float4 pw0 = *(const float4*)(Wp),     pw1 = *(const float4*)(Wp + 4);

    float acc[4][4][4] = {};

    for (int k0 = 0;;) {
        *(float4*)&As[lr][lc]   = cvt4(pa0);
        *(float4*)&As[lr][lc+4] = cvt4(pa1);
        *(float4*)&Ws[lr][lc]   = cvt4(pw0);
        *(float4*)&Ws[lr][lc+4] = cvt4(pw1);
        __syncthreads();

        const int kn = k0 + 16;
        if (kn < DMODEL) {
            pa0 = *(const float4*)(Ap + kn); pa1 = *(const float4*)(Ap + kn + 4);
            pw0 = *(const float4*)(Wp + kn); pw1 = *(const float4*)(Wp + kn + 4);
        }

#pragma unroll
        for (int ks = 0; ks < 2; ++ks) {
            const int kb = ks * 8;
            uint32_t af[4][4], bf[4][2];
#pragma unroll
            for (int mt = 0; mt < 4; ++mt)
                ldsm4(af[mt], As_b + (uint32_t)(((wm*64 + mt*16 + arow)*20 + kb + acol) * 4));
#pragma unroll
            for (int p = 0; p < 2; ++p) {
                uint32_t r[4];
                ldsm4(r, Ws_b + (uint32_t)(((wn*32 + p*16 + brow)*20 + kb + bcol) * 4));
                bf[p*2  ][0] = r[0]; bf[p*2  ][1] = r[1];
                bf[p*2+1][0] = r[2]; bf[p*2+1][1] = r[3];
            }
#pragma unroll
            for (int mt = 0; mt < 4; ++mt)
#pragma unroll
                for (int nt = 0; nt < 4; ++nt)
                    mma8(acc[mt][nt], af[mt], bf[nt]);
        }

        k0 = kn;
        if (k0 >= DMODEL) break;
        __syncthreads();
    }

    // epilogue
#pragma unroll
    for (int mt = 0; mt < 4; ++mt) {
        const int r0 = bm + wm*64 + mt*16 + g;
#pragma unroll
        for (int nt = 0; nt < 4; ++nt) {
            const int c0 = bn + wn*32 + nt*8 + t*2;
            const float bb0 = bias[c0], bb1 = bias[c0 + 1];
            const float v00 = acc[mt][nt][0] + bb0, v01 = acc[mt][nt][1] + bb1;
            const float v10 = acc[mt][nt][2] + bb0, v11 = acc[mt][nt][3] + bb1;
            if (SPLIT) {
                const int bb = r0 >> 11;
                const int s  = r0 & (SEQ - 1);
                const int h  = c0 >> 6;
                const int d  = c0 & 63;
                float* p0 = C + (((size_t)(bb*NH + h))*SEQ + s    )*DEPTH + d;
                float* p1 = C + (((size_t)(bb*NH + h))*SEQ + s + 8)*DEPTH + d;
                *(float2*)p0 = make_float2(v00, v01);
                *(float2*)p1 = make_float2(v10, v11);
            } else {
                *(float2*)(C + (size_t)r0      * DMODEL + c0) = make_float2(v00, v01);
                *(float2*)(C + (size_t)(r0+8)  * DMODEL + c0) = make_float2(v10, v11);
            }
        }
    }
}

// ---------------------------------------------------------------------------
// Flash attention, tf32 tensor cores + ldmatrix fragment loads.
// Block = 128 threads (4 warps), q-tile 64, kv-chunk 32.
// Q fragments in registers; K/V double-buffered smem; 1 sync per chunk.
// Smem: Ks[2][32][68] + Vt[2][64][36] + Ps[64][36] = 44.0 KB.
// ---------------------------------------------------------------------------
__global__ __launch_bounds__(128, 4)
void attn_tc(const float* __restrict__ Qh, const float* __restrict__ Kh,
             const float* __restrict__ Vh, const float* __restrict__ mask,
             float* __restrict__ Oc)
{
    __shared__ float Ks[2][32][68];
    __shared__ float Vt[2][64][36];
    __shared__ float Ps[64][36];

    const int tid  = threadIdx.x;
    const int lane = tid & 31, w = tid >> 5;
    const int g    = lane >> 2, t = lane & 3;
    const int bh   = blockIdx.x;         // b*NH + h
    const int qt   = blockIdx.y;
    const int b    = bh >> 4, h = bh & 15;

    // ldmatrix per-lane address components
    const int arow = lane & 15;
    const int acol = (lane >> 4) * 4;
    const int brow = ((lane >> 4) << 3) + (lane & 7);
    const int bcol = ((lane >> 3) & 1) * 4;

    const uint32_t Ks_b = (uint32_t)__cvta_generic_to_shared(&Ks[0][0][0]);
    const uint32_t Vt_b = (uint32_t)__cvta_generic_to_shared(&Vt[0][0][0]);
    const uint32_t Ps_b = (uint32_t)__cvta_generic_to_shared(&Ps[0][0]);

    // --- Q fragments -> registers (one-time) ---
    const float* Qb    = Qh + ((size_t)bh * SEQ + qt*64) * DEPTH;
    const float* qrow0 = Qb + (w*16 + g    ) * DEPTH;
    const float* qrow1 = Qb + (w*16 + g + 8) * DEPTH;
    uint32_t qf[8][4];
#pragma unroll
    for (int kb8 = 0; kb8 < 8; ++kb8) {
        qf[kb8][0] = __float_as_uint(to_tf32(__ldg(qrow0 + kb8*8 + t)));
        qf[kb8][1] = __float_as_uint(to_tf32(__ldg(qrow1 + kb8*8 + t)));
        qf[kb8][2] = __float_as_uint(to_tf32(__ldg(qrow0 + kb8*8 + t + 4)));
        qf[kb8][3] = __float_as_uint(to_tf32(__ldg(qrow1 + kb8*8 + t + 4)));
    }

    const float* Kb0 = Kh + (size_t)bh * SEQ * DEPTH;
    const float* Vb0 = Vh + (size_t)bh * SEQ * DEPTH;
    const float* Mb  = mask + ((size_t)b * SEQ + qt*64) * SEQ;
    const int pr = w*16 + g;

    // per-thread K/V load mapping
    const int kr  = tid >> 4;           // K rows: kr, kr+8, kr+16, kr+24
    const int kc4 = (tid & 15) * 4;
    const int vc  = tid & 31;           // V col (seq pos within chunk)
    const int vd4 = (tid >> 5) * 4;     // V depth base: vd4, +16, +32, +48

    float4 pk[4], pv[4];
#pragma unroll
    for (int j = 0; j < 4; ++j) {
        pk[j] = *(const float4*)(Kb0 + (size_t)(kr + j*8)*DEPTH + kc4);
        pv[j] = *(const float4*)(Vb0 + (size_t)vc*DEPTH + vd4 + j*16);
    }
#pragma unroll
    for (int j = 0; j < 4; ++j) {
        *(float4*)&Ks[0][kr + j*8][kc4] = cvt4(pk[j]);
        const int d = vd4 + j*16;
        Vt[0][d+0][vc] = to_tf32(pv[j].x); Vt[0][d+1][vc] = to_tf32(pv[j].y);
        Vt[0][d+2][vc] = to_tf32(pv[j].z); Vt[0][d+3][vc] = to_tf32(pv[j].w);
    }
#pragma unroll
    for (int j = 0; j < 4; ++j) {
        pk[j] = *(const float4*)(Kb0 + (size_t)(32 + kr + j*8)*DEPTH + kc4);
        pv[j] = *(const float4*)(Vb0 + (size_t)(32 + vc)*DEPTH + vd4 + j*16);
    }
    __syncthreads();

    float oacc[8][4] = {};
    float m0 = -INFINITY, m1 = -INFINITY, l0 = 0.f, l1 = 0.f;
    int buf = 0;

    for (int kt = 0; kt < NT; ++kt) {
        if (kt + 1 < NT) {
#pragma unroll
            for (int j = 0; j < 4; ++j) {
                *(float4*)&Ks[buf^1][kr + j*8][kc4] = cvt4(pk[j]);
                const int d = vd4 + j*16;
                Vt[buf^1][d+0][vc] = to_tf32(pv[j].x); Vt[buf^1][d+1][vc] = to_tf32(pv[j].y);
                Vt[buf^1][d+2][vc] = to_tf32(pv[j].z); Vt[buf^1][d+3][vc] = to_tf32(pv[j].w);
            }
            if (kt + 2 < NT) {
                const int base = (kt + 2) * 32;
#pragma unroll
                for (int j = 0; j < 4; ++j) {
                    pk[j] = *(const float4*)(Kb0 + (size_t)(base + kr + j*8)*DEPTH + kc4);
                    pv[j] = *(const float4*)(Vb0 + (size_t)(base + vc)*DEPTH + vd4 + j*16);
                }
            }
        }

        const uint32_t Ksb = Ks_b + (uint32_t)(buf * 32*68*4);
        const uint32_t Vtb = Vt_b + (uint32_t)(buf * 64*36*4);

        // S = Q @ K^T  (16x32 per warp)
        float sacc[4][4] = {};
#pragma unroll
        for (int ks = 0; ks < 8; ++ks) {
            const int kb = ks * 8;
            uint32_t bf[4][2];
#pragma unroll
            for (int p = 0; p < 2; ++p) {
                uint32_t r[4];
                ldsm4(r, Ksb + (uint32_t)(((p*16 + brow)*68 + kb + bcol) * 4));
                bf[p*2  ][0] = r[0]; bf[p*2  ][1] = r[1];
                bf[p*2+1][0] = r[2]; bf[p*2+1][1] = r[3];
            }
#pragma unroll
            for (int nt = 0; nt < 4; ++nt)
                mma8(sacc[nt], qf[ks], bf[nt]);
        }

        // scale + additive mask
#pragma unroll
        for (int nt = 0; nt < 4; ++nt) {
            const int c0 = kt*32 + nt*8 + t*2;
            float2 mlo = *(const float2*)(Mb + (size_t)(w*16 + g    )*SEQ + c0);
            float2 mhi = *(const float2*)(Mb + (size_t)(w*16 + g + 8)*SEQ + c0);
            sacc[nt][0] = fmaf(mlo.x, -1e9f, sacc[nt][0]*0.125f);
            sacc[nt][1] = fmaf(mlo.y, -1e9f, sacc[nt][1]*0.125f);
            sacc[nt][2] = fmaf(mhi.x, -1e9f, sacc[nt][2]*0.125f);
            sacc[nt][3] = fmaf(mhi.y, -1e9f, sacc[nt][3]*0.125f);
        }

        // online softmax (2 rows per thread, quad reduction over lane%4)
        float rm0 = -INFINITY, rm1 = -INFINITY;
#pragma unroll
        for (int nt = 0; nt < 4; ++nt) {
            rm0 = fmaxf(rm0, fmaxf(sacc[nt][0], sacc[nt][1]));
            rm1 = fmaxf(rm1, fmaxf(sacc[nt][2], sacc[nt][3]));
        }
        rm0 = fmaxf(rm0, __shfl_xor_sync(0xffffffffu, rm0, 1));
        rm0 = fmaxf(rm0, __shfl_xor_sync(0xffffffffu, rm0, 2));
        rm1 = fmaxf(rm1, __shfl_xor_sync(0xffffffffu, rm1, 1));
        rm1 = fmaxf(rm1, __shfl_xor_sync(0xffffffffu, rm1, 2));

        const float mn0 = fmaxf(m0, rm0), mn1 = fmaxf(m1, rm1);
        const float a0  = __expf(m0 - mn0), a1 = __expf(m1 - mn1);
        m0 = mn0; m1 = mn1;

        float sum0 = 0.f, sum1 = 0.f;
#pragma unroll
        for (int nt = 0; nt < 4; ++nt) {
            sacc[nt][0] = __expf(sacc[nt][0] - mn0); sum0 += sacc[nt][0];
            sacc[nt][1] = __expf(sacc[nt][1] - mn0); sum0 += sacc[nt][1];
            sacc[nt][2] = __expf(sacc[nt][2] - mn1); sum1 += sacc[nt][2];
            sacc[nt][3] = __expf(sacc[nt][3] - mn1); sum1 += sacc[nt][3];
        }
        sum0 += __shfl_xor_sync(0xffffffffu, sum0, 1);
        sum0 += __shfl_xor_sync(0xffffffffu, sum0, 2);
        sum1 += __shfl_xor_sync(0xffffffffu, sum1, 1);
        sum1 += __shfl_xor_sync(0xffffffffu, sum1, 2);
        l0 = l0*a0 + sum0;
        l1 = l1*a1 + sum1;
#pragma unroll
        for (int nt = 0; nt < 8; ++nt) {
            oacc[nt][0] *= a0; oacc[nt][1] *= a0;
            oacc[nt][2] *= a1; oacc[nt][3] *= a1;
        }

        // P -> smem (warp-private rows, tf32-rounded)
#pragma unroll
        for (int nt = 0; nt < 4; ++nt) {
            *(float2*)&Ps[pr    ][nt*8 + t*2] = make_float2(to_tf32(sacc[nt][0]), to_tf32(sacc[nt][1]));
            *(float2*)&Ps[pr + 8][nt*8 + t*2] = make_float2(to_tf32(sacc[nt][2]), to_tf32(sacc[nt][3]));
        }
        __syncwarp();

        // O += P @ V   (16x64 per warp, K=32)
#pragma unroll
        for (int ks = 0; ks < 4; ++ks) {
            const int kb = ks * 8;
            uint32_t af[4];
            ldsm4(af, Ps_b + (uint32_t)(((w*16 + arow)*36 + kb + acol) * 4));
            uint32_t bf[8][2];
#pragma unroll
            for (int p = 0; p < 4; ++p) {
                uint32_t r[4];
                ldsm4(r, Vtb + (uint32_t)(((p*16 + brow)*36 + kb + bcol) * 4));
                bf[p*2  ][0] = r[0]; bf[p*2  ][1] = r[1];
                bf[p*2+1][0] = r[2]; bf[p*2+1][1] = r[3];
            }
#pragma unroll
            for (int nt = 0; nt < 8; ++nt)
                mma8(oacc[nt], af, bf[nt]);
        }
        __syncthreads();
        buf ^= 1;
    }

    // epilogue: normalize + concat heads -> Oc[b*S + s][h*64 + d]
    const float inv0 = 1.f / l0, inv1 = 1.f / l1;
    const size_t row0 = (size_t)b*SEQ + qt*64 + w*16 + g;
#pragma unroll
    for (int nt = 0; nt < 8; ++nt) {
        const int c = h*64 + nt*8 + t*2;
        *(float2*)(Oc + row0     * DMODEL + c) = make_float2(oacc[nt][0]*inv0, oacc[nt][1]*inv0);
        *(float2*)(Oc + (row0+8) * DMODEL + c) = make_float2(oacc[nt][2]*inv1, oacc[nt][3]*inv1);
    }
}

// ---------------------------------------------------------------------------
extern "C" void kernel_launch(void* const* d_in, const int* in_sizes, int n_in,
                              void* d_out, int out_size)
{
    const float* v    = (const float*)d_in[0];
    const float* k    = (const float*)d_in[1];
    const float* q    = (const float*)d_in[2];
    const float* mask = (const float*)d_in[3];
    const float* wq   = (const float*)d_in[4];
    const float* bq   = (const float*)d_in[5];
    const float* wk   = (const float*)d_in[6];
    const float* bk   = (const float*)d_in[7];
    const float* wv   = (const float*)d_in[8];
    const float* bv   = (const float*)d_in[9];
    const float* wo   = (const float*)d_in[10];
    const float* bo   = (const float*)d_in[11];
    float* out = (float*)d_out;

    float *Qh, *Kh, *Vh, *Oc;
    cudaGetSymbolAddress((void**)&Qh, g_Qh);
    cudaGetSymbolAddress((void**)&Kh, g_Kh);
    cudaGetSymbolAddress((void**)&Vh, g_Vh);
    cudaGetSymbolAddress((void**)&Oc, g_Oc);

    // fused Q/K/V projections: one launch, blockIdx.z selects the GEMM
    dim3 gqkv(DMODEL/128, MROWS/128, 3);  // (8, 32, 3)
    gemm_tc<true, true><<<gqkv, 256>>>(q, wq, bq, Qh,
                                       k, wk, bk, Kh,
                                       v, wv, bv, Vh);

    dim3 ga(BATCH*NH, SEQ/64);            // (32, 32)
    attn_tc<<<ga, 128>>>(Qh, Kh, Vh, mask, Oc);

    dim3 gg(DMODEL/128, MROWS/128);       // (8, 32)
    gemm_tc<false, false><<<gg, 256>>>(Oc, wo, bo, out,
                                       nullptr, nullptr, nullptr, nullptr,
                                       nullptr, nullptr, nullptr, nullptr);
}

// round 12
// speedup vs baseline: 1.9297x; 1.0925x over previous
#include <cuda_runtime.h>
#include <math.h>
#include <stdint.h>

#define DMODEL 1024
#define NH     16
#define DEPTH  64
#define BATCH  2
#define SEQ    2048
#define MROWS  (BATCH*SEQ)   // 4096
#define NT     (SEQ/32)      // 64 kv chunks

// Scratch (allocation-free rule: __device__ globals)
__device__ float g_Qh[BATCH*NH*SEQ*DEPTH];
__device__ float g_Kh[BATCH*NH*SEQ*DEPTH];
__device__ float g_Vh[BATCH*NH*SEQ*DEPTH];
__device__ float g_Oc[MROWS*DMODEL];

__device__ __forceinline__ float to_tf32(float x) {
    float r;
    asm("cvt.rna.tf32.f32 %0, %1;" : "=f"(r) : "f"(x));
    return r;
}
__device__ __forceinline__ float4 cvt4(float4 v) {
    return make_float4(to_tf32(v.x), to_tf32(v.y), to_tf32(v.z), to_tf32(v.w));
}
__device__ __forceinline__ uint32_t cvtu(uint32_t u) {
    return __float_as_uint(to_tf32(__uint_as_float(u)));
}

__device__ __forceinline__ void mma8(float c[4], const uint32_t a[4], const uint32_t b[2]) {
    asm volatile(
        "mma.sync.aligned.m16n8k8.row.col.f32.tf32.tf32.f32 "
        "{%0,%1,%2,%3},{%4,%5,%6,%7},{%8,%9},{%0,%1,%2,%3};\n"
        : "+f"(c[0]), "+f"(c[1]), "+f"(c[2]), "+f"(c[3])
        : "r"(a[0]), "r"(a[1]), "r"(a[2]), "r"(a[3]), "r"(b[0]), "r"(b[1]));
}

// ldmatrix x4: four 8x4-tf32 tiles in one instruction.
__device__ __forceinline__ void ldsm4(uint32_t* r, uint32_t addr) {
    asm volatile("ldmatrix.sync.aligned.m8n8.x4.shared.b16 {%0,%1,%2,%3}, [%4];"
                 : "=r"(r[0]), "=r"(r[1]), "=r"(r[2]), "=r"(r[3]) : "r"(addr));
}

__device__ __forceinline__ void cpasync16(uint32_t dst, const void* src) {
    asm volatile("cp.async.ca.shared.global [%0], [%1], 16;\n" :: "r"(dst), "l"(src));
}
__device__ __forceinline__ void cp_commit() {
    asm volatile("cp.async.commit_group;\n");
}
template<int N>
__device__ __forceinline__ void cp_wait() {
    asm volatile("cp.async.wait_group %0;\n" :: "n"(N));
}

// ---------------------------------------------------------------------------
// C = A[4096,1024] @ W[1024,1024]^T + bias, tf32 tensor-core GEMM.
// 128x128 tile, BK=16, cp.async 2-stage double buffer, ldmatrix fragments,
// tf32 cvt applied post-ldmatrix (bit-identical numerics).
// QKV=true fuses the 3 projections via blockIdx.z.
// ---------------------------------------------------------------------------
template<bool SPLIT, bool QKV>
__global__ __launch_bounds__(256)
void gemm_tc(const float* __restrict__ A0, const float* __restrict__ W0,
             const float* __restrict__ b0, float* __restrict__ C0,
             const float* __restrict__ A1, const float* __restrict__ W1,
             const float* __restrict__ b1, float* __restrict__ C1,
             const float* __restrict__ A2, const float* __restrict__ W2,
             const float* __restrict__ b2, float* __restrict__ C2)
{
    __shared__ __align__(16) float As[2][128][20];   // 20 KB
    __shared__ __align__(16) float Ws[2][128][20];   // 20 KB

    const float* A    = A0;
    const float* W    = W0;
    const float* bias = b0;
    float*       C    = C0;
    if (QKV) {
        const int z = blockIdx.z;
        if (z == 1) { A = A1; W = W1; bias = b1; C = C1; }
        else if (z == 2) { A = A2; W = W2; bias = b2; C = C2; }
    }

    const int tid  = threadIdx.x;
    const int lane = tid & 31, wid = tid >> 5;
    const int wm   = wid >> 2, wn = wid & 3;
    const int g    = lane >> 2, t = lane & 3;
    const int bm   = blockIdx.y * 128, bn = blockIdx.x * 128;

    // ldmatrix per-lane address components
    const int arow = lane & 15;                            // A-frag row offset
    const int acol = (lane >> 4) * 4;                      // A-frag col offset (0|4)
    const int brow = ((lane >> 4) << 3) + (lane & 7);      // B-frag row offset
    const int bcol = ((lane >> 3) & 1) * 4;                // B-frag col offset (0|4)

    const uint32_t As_s = (uint32_t)__cvta_generic_to_shared(&As[0][0][0]);
    const uint32_t Ws_s = (uint32_t)__cvta_generic_to_shared(&Ws[0][0][0]);
    const uint32_t STAGE = 128u * 20u * 4u;               // 10240 B per stage

    // cp.async mapping: per stage, A tile = 128 rows x 4 x 16B segs = 512 segs.
    // Thread handles segs tid and tid+256 -> rows (tid>>2) and (tid>>2)+64.
    const int crow = tid >> 2;            // 0..63
    const int csc  = (tid & 3) * 4;       // 0,4,8,12 (floats)
    const float* Arow0 = A + (size_t)(bm + crow     ) * DMODEL + csc;
    const float* Arow1 = A + (size_t)(bm + crow + 64) * DMODEL + csc;
    const float* Wrow0 = W + (size_t)(bn + crow     ) * DMODEL + csc;
    const float* Wrow1 = W + (size_t)(bn + crow + 64) * DMODEL + csc;
    const uint32_t Ad0 = As_s + (uint32_t)((crow      * 20 + csc) * 4);
    const uint32_t Ad1 = As_s + (uint32_t)(((crow+64) * 20 + csc) * 4);
    const uint32_t Wd0 = Ws_s + (uint32_t)((crow      * 20 + csc) * 4);
    const uint32_t Wd1 = Ws_s + (uint32_t)(((crow+64) * 20 + csc) * 4);

#define GEMM_ISSUE(st, k0)                                   \
    do {                                                     \
        const uint32_t so = (st) * STAGE;                    \
        cpasync16(Ad0 + so, Arow0 + (k0));                   \
        cpasync16(Ad1 + so, Arow1 + (k0));                   \
        cpasync16(Wd0 + so, Wrow0 + (k0));                   \
        cpasync16(Wd1 + so, Wrow1 + (k0));                   \
        cp_commit();                                         \
    } while (0)

    // prologue: stages for k=0 and k=16
    GEMM_ISSUE(0, 0);
    GEMM_ISSUE(1, 16);
    cp_wait<1>();
    __syncthreads();

    float acc[4][4][4] = {};
    const int NI = DMODEL / 16;   // 64

    for (int i = 0; i < NI; ++i) {
        const int cur = i & 1;
        const uint32_t Asb = As_s + (uint32_t)cur * STAGE;
        const uint32_t Wsb = Ws_s + (uint32_t)cur * STAGE;

#pragma unroll
        for (int ks = 0; ks < 2; ++ks) {
            const int kb = ks * 8;
            uint32_t af[4][4], bf[4][2];
#pragma unroll
            for (int mt = 0; mt < 4; ++mt) {
                ldsm4(af[mt], Asb + (uint32_t)(((wm*64 + mt*16 + arow)*20 + kb + acol) * 4));
#pragma unroll
                for (int j = 0; j < 4; ++j) af[mt][j] = cvtu(af[mt][j]);
            }
#pragma unroll
            for (int p = 0; p < 2; ++p) {
                uint32_t r[4];
                ldsm4(r, Wsb + (uint32_t)(((wn*32 + p*16 + brow)*20 + kb + bcol) * 4));
                bf[p*2  ][0] = cvtu(r[0]); bf[p*2  ][1] = cvtu(r[1]);
                bf[p*2+1][0] = cvtu(r[2]); bf[p*2+1][1] = cvtu(r[3]);
            }
#pragma unroll
            for (int mt = 0; mt < 4; ++mt)
#pragma unroll
                for (int nt = 0; nt < 4; ++nt)
                    mma8(acc[mt][nt], af[mt], bf[nt]);
        }

        __syncthreads();                    // all warps done reading stage cur
        if (i + 2 < NI) {
            GEMM_ISSUE(cur, (i + 2) * 16);  // overwrite drained stage
            cp_wait<1>();                   // stage for iter i+1 complete
        } else {
            cp_wait<0>();
        }
        __syncthreads();                    // completion visible block-wide
    }
#undef GEMM_ISSUE

    // epilogue
#pragma unroll
    for (int mt = 0; mt < 4; ++mt) {
        const int r0 = bm + wm*64 + mt*16 + g;
#pragma unroll
        for (int nt = 0; nt < 4; ++nt) {
            const int c0 = bn + wn*32 + nt*8 + t*2;
            const float bb0 = bias[c0], bb1 = bias[c0 + 1];
            const float v00 = acc[mt][nt][0] + bb0, v01 = acc[mt][nt][1] + bb1;
            const float v10 = acc[mt][nt][2] + bb0, v11 = acc[mt][nt][3] + bb1;
            if (SPLIT) {
                const int bb = r0 >> 11;
                const int s  = r0 & (SEQ - 1);
                const int h  = c0 >> 6;
                const int d  = c0 & 63;
                float* p0 = C + (((size_t)(bb*NH + h))*SEQ + s    )*DEPTH + d;
                float* p1 = C + (((size_t)(bb*NH + h))*SEQ + s + 8)*DEPTH + d;
                *(float2*)p0 = make_float2(v00, v01);
                *(float2*)p1 = make_float2(v10, v11);
            } else {
                *(float2*)(C + (size_t)r0      * DMODEL + c0) = make_float2(v00, v01);
                *(float2*)(C + (size_t)(r0+8)  * DMODEL + c0) = make_float2(v10, v11);
            }
        }
    }
}

// ---------------------------------------------------------------------------
// Flash attention, tf32 tensor cores + ldmatrix fragment loads.
// (unchanged from round 11 — proven)
// ---------------------------------------------------------------------------
__global__ __launch_bounds__(128, 4)
void attn_tc(const float* __restrict__ Qh, const float* __restrict__ Kh,
             const float* __restrict__ Vh, const float* __restrict__ mask,
             float* __restrict__ Oc)
{
    __shared__ float Ks[2][32][68];
    __shared__ float Vt[2][64][36];
    __shared__ float Ps[64][36];

    const int tid  = threadIdx.x;
    const int lane = tid & 31, w = tid >> 5;
    const int g    = lane >> 2, t = lane & 3;
    const int bh   = blockIdx.x;         // b*NH + h
    const int qt   = blockIdx.y;
    const int b    = bh >> 4, h = bh & 15;

    const int arow = lane & 15;
    const int acol = (lane >> 4) * 4;
    const int brow = ((lane >> 4) << 3) + (lane & 7);
    const int bcol = ((lane >> 3) & 1) * 4;

    const uint32_t Ks_b = (uint32_t)__cvta_generic_to_shared(&Ks[0][0][0]);
    const uint32_t Vt_b = (uint32_t)__cvta_generic_to_shared(&Vt[0][0][0]);
    const uint32_t Ps_b = (uint32_t)__cvta_generic_to_shared(&Ps[0][0]);

    // --- Q fragments -> registers (one-time) ---
    const float* Qb    = Qh + ((size_t)bh * SEQ + qt*64) * DEPTH;
    const float* qrow0 = Qb + (w*16 + g    ) * DEPTH;
    const float* qrow1 = Qb + (w*16 + g + 8) * DEPTH;
    uint32_t qf[8][4];
#pragma unroll
    for (int kb8 = 0; kb8 < 8; ++kb8) {
        qf[kb8][0] = __float_as_uint(to_tf32(__ldg(qrow0 + kb8*8 + t)));
        qf[kb8][1] = __float_as_uint(to_tf32(__ldg(qrow1 + kb8*8 + t)));
        qf[kb8][2] = __float_as_uint(to_tf32(__ldg(qrow0 + kb8*8 + t + 4)));
        qf[kb8][3] = __float_as_uint(to_tf32(__ldg(qrow1 + kb8*8 + t + 4)));
    }

    const float* Kb0 = Kh + (size_t)bh * SEQ * DEPTH;
    const float* Vb0 = Vh + (size_t)bh * SEQ * DEPTH;
    const float* Mb  = mask + ((size_t)b * SEQ + qt*64) * SEQ;
    const int pr = w*16 + g;

    const int kr  = tid >> 4;           // K rows: kr, kr+8, kr+16, kr+24
    const int kc4 = (tid & 15) * 4;
    const int vc  = tid & 31;           // V col (seq pos within chunk)
    const int vd4 = (tid >> 5) * 4;     // V depth base: vd4, +16, +32, +48

    float4 pk[4], pv[4];
#pragma unroll
    for (int j = 0; j < 4; ++j) {
        pk[j] = *(const float4*)(Kb0 + (size_t)(kr + j*8)*DEPTH + kc4);
        pv[j] = *(const float4*)(Vb0 + (size_t)vc*DEPTH + vd4 + j*16);
    }
#pragma unroll
    for (int j = 0; j < 4; ++j) {
        *(float4*)&Ks[0][kr + j*8][kc4] = cvt4(pk[j]);
        const int d = vd4 + j*16;
        Vt[0][d+0][vc] = to_tf32(pv[j].x); Vt[0][d+1][vc] = to_tf32(pv[j].y);
        Vt[0][d+2][vc] = to_tf32(pv[j].z); Vt[0][d+3][vc] = to_tf32(pv[j].w);
    }
#pragma unroll
    for (int j = 0; j < 4; ++j) {
        pk[j] = *(const float4*)(Kb0 + (size_t)(32 + kr + j*8)*DEPTH + kc4);
        pv[j] = *(const float4*)(Vb0 + (size_t)(32 + vc)*DEPTH + vd4 + j*16);
    }
    __syncthreads();

    float oacc[8][4] = {};
    float m0 = -INFINITY, m1 = -INFINITY, l0 = 0.f, l1 = 0.f;
    int buf = 0;

    for (int kt = 0; kt < NT; ++kt) {
        if (kt + 1 < NT) {
#pragma unroll
            for (int j = 0; j < 4; ++j) {
                *(float4*)&Ks[buf^1][kr + j*8][kc4] = cvt4(pk[j]);
                const int d = vd4 + j*16;
                Vt[buf^1][d+0][vc] = to_tf32(pv[j].x); Vt[buf^1][d+1][vc] = to_tf32(pv[j].y);
                Vt[buf^1][d+2][vc] = to_tf32(pv[j].z); Vt[buf^1][d+3][vc] = to_tf32(pv[j].w);
            }
            if (kt + 2 < NT) {
                const int base = (kt + 2) * 32;
#pragma unroll
                for (int j = 0; j < 4; ++j) {
                    pk[j] = *(const float4*)(Kb0 + (size_t)(base + kr + j*8)*DEPTH + kc4);
                    pv[j] = *(const float4*)(Vb0 + (size_t)(base + vc)*DEPTH + vd4 + j*16);
                }
            }
        }

        const uint32_t Ksb = Ks_b + (uint32_t)(buf * 32*68*4);
        const uint32_t Vtb = Vt_b + (uint32_t)(buf * 64*36*4);

        // S = Q @ K^T  (16x32 per warp)
        float sacc[4][4] = {};
#pragma unroll
        for (int ks = 0; ks < 8; ++ks) {
            const int kb = ks * 8;
            uint32_t bf[4][2];
#pragma unroll
            for (int p = 0; p < 2; ++p) {
                uint32_t r[4];
                ldsm4(r, Ksb + (uint32_t)(((p*16 + brow)*68 + kb + bcol) * 4));
                bf[p*2  ][0] = r[0]; bf[p*2  ][1] = r[1];
                bf[p*2+1][0] = r[2]; bf[p*2+1][1] = r[3];
            }
#pragma unroll
            for (int nt = 0; nt < 4; ++nt)
                mma8(sacc[nt], qf[ks], bf[nt]);
        }

        // scale + additive mask
#pragma unroll
        for (int nt = 0; nt < 4; ++nt) {
            const int c0 = kt*32 + nt*8 + t*2;
            float2 mlo = *(const float2*)(Mb + (size_t)(w*16 + g    )*SEQ + c0);
            float2 mhi = *(const float2*)(Mb + (size_t)(w*16 + g + 8)*SEQ + c0);
            sacc[nt][0] = fmaf(mlo.x, -1e9f, sacc[nt][0]*0.125f);
            sacc[nt][1] = fmaf(mlo.y, -1e9f, sacc[nt][1]*0.125f);
            sacc[nt][2] = fmaf(mhi.x, -1e9f, sacc[nt][2]*0.125f);
            sacc[nt][3] = fmaf(mhi.y, -1e9f, sacc[nt][3]*0.125f);
        }

        // online softmax
        float rm0 = -INFINITY, rm1 = -INFINITY;
#pragma unroll
        for (int nt = 0; nt < 4; ++nt) {
            rm0 = fmaxf(rm0, fmaxf(sacc[nt][0], sacc[nt][1]));
            rm1 = fmaxf(rm1, fmaxf(sacc[nt][2], sacc[nt][3]));
        }
        rm0 = fmaxf(rm0, __shfl_xor_sync(0xffffffffu, rm0, 1));
        rm0 = fmaxf(rm0, __shfl_xor_sync(0xffffffffu, rm0, 2));
        rm1 = fmaxf(rm1, __shfl_xor_sync(0xffffffffu, rm1, 1));
        rm1 = fmaxf(rm1, __shfl_xor_sync(0xffffffffu, rm1, 2));

        const float mn0 = fmaxf(m0, rm0), mn1 = fmaxf(m1, rm1);
        const float a0  = __expf(m0 - mn0), a1 = __expf(m1 - mn1);
        m0 = mn0; m1 = mn1;

        float sum0 = 0.f, sum1 = 0.f;
#pragma unroll
        for (int nt = 0; nt < 4; ++nt) {
            sacc[nt][0] = __expf(sacc[nt][0] - mn0); sum0 += sacc[nt][0];
            sacc[nt][1] = __expf(sacc[nt][1] - mn0); sum0 += sacc[nt][1];
            sacc[nt][2] = __expf(sacc[nt][2] - mn1); sum1 += sacc[nt][2];
            sacc[nt][3] = __expf(sacc[nt][3] - mn1); sum1 += sacc[nt][3];
        }
        sum0 += __shfl_xor_sync(0xffffffffu, sum0, 1);
        sum0 += __shfl_xor_sync(0xffffffffu, sum0, 2);
        sum1 += __shfl_xor_sync(0xffffffffu, sum1, 1);
        sum1 += __shfl_xor_sync(0xffffffffu, sum1, 2);
        l0 = l0*a0 + sum0;
        l1 = l1*a1 + sum1;
#pragma unroll
        for (int nt = 0; nt < 8; ++nt) {
            oacc[nt][0] *= a0; oacc[nt][1] *= a0;
            oacc[nt][2] *= a1; oacc[nt][3] *= a1;
        }

        // P -> smem (warp-private rows, tf32-rounded)
#pragma unroll
        for (int nt = 0; nt < 4; ++nt) {
            *(float2*)&Ps[pr    ][nt*8 + t*2] = make_float2(to_tf32(sacc[nt][0]), to_tf32(sacc[nt][1]));
            *(float2*)&Ps[pr + 8][nt*8 + t*2] = make_float2(to_tf32(sacc[nt][2]), to_tf32(sacc[nt][3]));
        }
        __syncwarp();

        // O += P @ V   (16x64 per warp, K=32)
#pragma unroll
        for (int ks = 0; ks < 4; ++ks) {
            const int kb = ks * 8;
            uint32_t af[4];
            ldsm4(af, Ps_b + (uint32_t)(((w*16 + arow)*36 + kb + acol) * 4));
            uint32_t bf[8][2];
#pragma unroll
            for (int p = 0; p < 4; ++p) {
                uint32_t r[4];
                ldsm4(r, Vtb + (uint32_t)(((p*16 + brow)*36 + kb + bcol) * 4));
                bf[p*2  ][0] = r[0]; bf[p*2  ][1] = r[1];
                bf[p*2+1][0] = r[2]; bf[p*2+1][1] = r[3];
            }
#pragma unroll
            for (int nt = 0; nt < 8; ++nt)
                mma8(oacc[nt], af, bf[nt]);
        }
        __syncthreads();
        buf ^= 1;
    }

    // epilogue: normalize + concat heads -> Oc[b*S + s][h*64 + d]
    const float inv0 = 1.f / l0, inv1 = 1.f / l1;
    const size_t row0 = (size_t)b*SEQ + qt*64 + w*16 + g;
#pragma unroll
    for (int nt = 0; nt < 8; ++nt) {
        const int c = h*64 + nt*8 + t*2;
        *(float2*)(Oc + row0     * DMODEL + c) = make_float2(oacc[nt][0]*inv0, oacc[nt][1]*inv0);
        *(float2*)(Oc + (row0+8) * DMODEL + c) = make_float2(oacc[nt][2]*inv1, oacc[nt][3]*inv1);
    }
}

// ---------------------------------------------------------------------------
extern "C" void kernel_launch(void* const* d_in, const int* in_sizes, int n_in,
                              void* d_out, int out_size)
{
    const float* v    = (const float*)d_in[0];
    const float* k    = (const float*)d_in[1];
    const float* q    = (const float*)d_in[2];
    const float* mask = (const float*)d_in[3];
    const float* wq   = (const float*)d_in[4];
    const float* bq   = (const float*)d_in[5];
    const float* wk   = (const float*)d_in[6];
    const float* bk   = (const float*)d_in[7];
    const float* wv   = (const float*)d_in[8];
    const float* bv   = (const float*)d_in[9];
    const float* wo   = (const float*)d_in[10];
    const float* bo   = (const float*)d_in[11];
    float* out = (float*)d_out;

    float *Qh, *Kh, *Vh, *Oc;
    cudaGetSymbolAddress((void**)&Qh, g_Qh);
    cudaGetSymbolAddress((void**)&Kh, g_Kh);
    cudaGetSymbolAddress((void**)&Vh, g_Vh);
    cudaGetSymbolAddress((void**)&Oc, g_Oc);

    // fused Q/K/V projections: one launch, blockIdx.z selects the GEMM
    dim3 gqkv(DMODEL/128, MROWS/128, 3);  // (8, 32, 3)
    gemm_tc<true, true><<<gqkv, 256>>>(q, wq, bq, Qh,
                                       k, wk, bk, Kh,
                                       v, wv, bv, Vh);

    dim3 ga(BATCH*NH, SEQ/64);            // (32, 32)
    attn_tc<<<ga, 128>>>(Qh, Kh, Vh, mask, Oc);

    dim3 gg(DMODEL/128, MROWS/128);       // (8, 32)
    gemm_tc<false, false><<<gg, 256>>>(Oc, wo, bo, out,
                                       nullptr, nullptr, nullptr, nullptr,
                                       nullptr, nullptr, nullptr, nullptr);
}

// round 13
// speedup vs baseline: 2.1608x; 1.1198x over previous
#include <cuda_runtime.h>
#include <math.h>
#include <stdint.h>

#define DMODEL 1024
#define NH     16
#define DEPTH  64
#define BATCH  2
#define SEQ    2048
#define MROWS  (BATCH*SEQ)   // 4096
#define NT     (SEQ/32)      // 64 kv chunks

// Scratch (allocation-free rule: __device__ globals)
__device__ float g_Qh[BATCH*NH*SEQ*DEPTH];
__device__ float g_Kh[BATCH*NH*SEQ*DEPTH];
__device__ float g_VhT[BATCH*NH*DEPTH*SEQ];   // V stored transposed: [b,h,d,s]
__device__ float g_Oc[MROWS*DMODEL];

__device__ __forceinline__ float to_tf32(float x) {
    float r;
    asm("cvt.rna.tf32.f32 %0, %1;" : "=f"(r) : "f"(x));
    return r;
}
__device__ __forceinline__ uint32_t cvtu(uint32_t u) {
    return __float_as_uint(to_tf32(__uint_as_float(u)));
}

__device__ __forceinline__ void mma8(float c[4], const uint32_t a[4], const uint32_t b[2]) {
    asm volatile(
        "mma.sync.aligned.m16n8k8.row.col.f32.tf32.tf32.f32 "
        "{%0,%1,%2,%3},{%4,%5,%6,%7},{%8,%9},{%0,%1,%2,%3};\n"
        : "+f"(c[0]), "+f"(c[1]), "+f"(c[2]), "+f"(c[3])
        : "r"(a[0]), "r"(a[1]), "r"(a[2]), "r"(a[3]), "r"(b[0]), "r"(b[1]));
}

__device__ __forceinline__ void ldsm4(uint32_t* r, uint32_t addr) {
    asm volatile("ldmatrix.sync.aligned.m8n8.x4.shared.b16 {%0,%1,%2,%3}, [%4];"
                 : "=r"(r[0]), "=r"(r[1]), "=r"(r[2]), "=r"(r[3]) : "r"(addr));
}

__device__ __forceinline__ void cpasync16(uint32_t dst, const void* src) {
    asm volatile("cp.async.ca.shared.global [%0], [%1], 16;\n" :: "r"(dst), "l"(src));
}
__device__ __forceinline__ void cp_commit() {
    asm volatile("cp.async.commit_group;\n");
}
template<int N>
__device__ __forceinline__ void cp_wait() {
    asm volatile("cp.async.wait_group %0;\n" :: "n"(N));
}

// ---------------------------------------------------------------------------
// C = A[4096,1024] @ W[1024,1024]^T + bias, tf32 tensor-core GEMM.
// 128x128 tile, BK=16, cp.async 2-stage double buffer, ldmatrix fragments,
// tf32 cvt post-ldmatrix. QKV=true fuses the 3 projections via blockIdx.z;
// z==2 (V) writes output TRANSPOSED per head: [b,h,d,s].
// ---------------------------------------------------------------------------
template<bool SPLIT, bool QKV>
__global__ __launch_bounds__(256)
void gemm_tc(const float* __restrict__ A0, const float* __restrict__ W0,
             const float* __restrict__ b0, float* __restrict__ C0,
             const float* __restrict__ A1, const float* __restrict__ W1,
             const float* __restrict__ b1, float* __restrict__ C1,
             const float* __restrict__ A2, const float* __restrict__ W2,
             const float* __restrict__ b2, float* __restrict__ C2)
{
    __shared__ __align__(16) float As[2][128][20];
    __shared__ __align__(16) float Ws[2][128][20];

    const float* A    = A0;
    const float* W    = W0;
    const float* bias = b0;
    float*       C    = C0;
    if (QKV) {
        const int z = blockIdx.z;
        if (z == 1) { A = A1; W = W1; bias = b1; C = C1; }
        else if (z == 2) { A = A2; W = W2; bias = b2; C = C2; }
    }

    const int tid  = threadIdx.x;
    const int lane = tid & 31, wid = tid >> 5;
    const int wm   = wid >> 2, wn = wid & 3;
    const int g    = lane >> 2, t = lane & 3;
    const int bm   = blockIdx.y * 128, bn = blockIdx.x * 128;

    const int arow = lane & 15;
    const int acol = (lane >> 4) * 4;
    const int brow = ((lane >> 4) << 3) + (lane & 7);
    const int bcol = ((lane >> 3) & 1) * 4;

    const uint32_t As_s = (uint32_t)__cvta_generic_to_shared(&As[0][0][0]);
    const uint32_t Ws_s = (uint32_t)__cvta_generic_to_shared(&Ws[0][0][0]);
    const uint32_t STAGE = 128u * 20u * 4u;

    const int crow = tid >> 2;
    const int csc  = (tid & 3) * 4;
    const float* Arow0 = A + (size_t)(bm + crow     ) * DMODEL + csc;
    const float* Arow1 = A + (size_t)(bm + crow + 64) * DMODEL + csc;
    const float* Wrow0 = W + (size_t)(bn + crow     ) * DMODEL + csc;
    const float* Wrow1 = W + (size_t)(bn + crow + 64) * DMODEL + csc;
    const uint32_t Ad0 = As_s + (uint32_t)((crow      * 20 + csc) * 4);
    const uint32_t Ad1 = As_s + (uint32_t)(((crow+64) * 20 + csc) * 4);
    const uint32_t Wd0 = Ws_s + (uint32_t)((crow      * 20 + csc) * 4);
    const uint32_t Wd1 = Ws_s + (uint32_t)(((crow+64) * 20 + csc) * 4);

#define GEMM_ISSUE(st, k0)                                   \
    do {                                                     \
        const uint32_t so = (st) * STAGE;                    \
        cpasync16(Ad0 + so, Arow0 + (k0));                   \
        cpasync16(Ad1 + so, Arow1 + (k0));                   \
        cpasync16(Wd0 + so, Wrow0 + (k0));                   \
        cpasync16(Wd1 + so, Wrow1 + (k0));                   \
        cp_commit();                                         \
    } while (0)

    GEMM_ISSUE(0, 0);
    GEMM_ISSUE(1, 16);
    cp_wait<1>();
    __syncthreads();

    float acc[4][4][4] = {};
    const int NI = DMODEL / 16;   // 64

    for (int i = 0; i < NI; ++i) {
        const int cur = i & 1;
        const uint32_t Asb = As_s + (uint32_t)cur * STAGE;
        const uint32_t Wsb = Ws_s + (uint32_t)cur * STAGE;

#pragma unroll
        for (int ks = 0; ks < 2; ++ks) {
            const int kb = ks * 8;
            uint32_t af[4][4], bf[4][2];
#pragma unroll
            for (int mt = 0; mt < 4; ++mt) {
                ldsm4(af[mt], Asb + (uint32_t)(((wm*64 + mt*16 + arow)*20 + kb + acol) * 4));
#pragma unroll
                for (int j = 0; j < 4; ++j) af[mt][j] = cvtu(af[mt][j]);
            }
#pragma unroll
            for (int p = 0; p < 2; ++p) {
                uint32_t r[4];
                ldsm4(r, Wsb + (uint32_t)(((wn*32 + p*16 + brow)*20 + kb + bcol) * 4));
                bf[p*2  ][0] = cvtu(r[0]); bf[p*2  ][1] = cvtu(r[1]);
                bf[p*2+1][0] = cvtu(r[2]); bf[p*2+1][1] = cvtu(r[3]);
            }
#pragma unroll
            for (int mt = 0; mt < 4; ++mt)
#pragma unroll
                for (int nt = 0; nt < 4; ++nt)
                    mma8(acc[mt][nt], af[mt], bf[nt]);
        }

        __syncthreads();
        if (i + 2 < NI) {
            GEMM_ISSUE(cur, (i + 2) * 16);
            cp_wait<1>();
        } else {
            cp_wait<0>();
        }
        __syncthreads();
    }
#undef GEMM_ISSUE

    // epilogue
    const bool vtrans = QKV && (blockIdx.z == 2);
#pragma unroll
    for (int mt = 0; mt < 4; ++mt) {
        const int r0 = bm + wm*64 + mt*16 + g;
#pragma unroll
        for (int nt = 0; nt < 4; ++nt) {
            const int c0 = bn + wn*32 + nt*8 + t*2;
            const float bb0 = bias[c0], bb1 = bias[c0 + 1];
            const float v00 = acc[mt][nt][0] + bb0, v01 = acc[mt][nt][1] + bb1;
            const float v10 = acc[mt][nt][2] + bb0, v11 = acc[mt][nt][3] + bb1;
            if (SPLIT) {
                const int bb = r0 >> 11;
                const int s  = r0 & (SEQ - 1);
                const int h  = c0 >> 6;
                const int d  = c0 & 63;
                if (vtrans) {
                    // VT layout [b,h,d,s]
                    float* base = C + (((size_t)(bb*NH + h))*DEPTH + d)*SEQ + s;
                    base[0]       = v00;  base[SEQ]     = v01;
                    base[8]       = v10;  base[SEQ + 8] = v11;
                } else {
                    float* p0 = C + (((size_t)(bb*NH + h))*SEQ + s    )*DEPTH + d;
                    float* p1 = C + (((size_t)(bb*NH + h))*SEQ + s + 8)*DEPTH + d;
                    *(float2*)p0 = make_float2(v00, v01);
                    *(float2*)p1 = make_float2(v10, v11);
                }
            } else {
                *(float2*)(C + (size_t)r0      * DMODEL + c0) = make_float2(v00, v01);
                *(float2*)(C + (size_t)(r0+8)  * DMODEL + c0) = make_float2(v10, v11);
            }
        }
    }
}

// ---------------------------------------------------------------------------
// Flash attention, tf32 tensor cores, cp.async K/V pipeline.
// Block = 128 threads (4 warps), q-tile 64, kv-chunk 32.
// Q fragments in registers; V pre-transposed globally ([b,h,d,s]) so both
// K and V tiles are contiguous-row cp.async copies. tf32 cvt post-ldmatrix.
// Smem: Ks[2][32][68] + Vt[2][64][36] + Ps[64][36] = 44.0 KB.
// ---------------------------------------------------------------------------
__global__ __launch_bounds__(128, 4)
void attn_tc(const float* __restrict__ Qh, const float* __restrict__ Kh,
             const float* __restrict__ VhT, const float* __restrict__ mask,
             float* __restrict__ Oc)
{
    __shared__ __align__(16) float Ks[2][32][68];
    __shared__ __align__(16) float Vt[2][64][36];
    __shared__ __align__(16) float Ps[64][36];

    const int tid  = threadIdx.x;
    const int lane = tid & 31, w = tid >> 5;
    const int g    = lane >> 2, t = lane & 3;
    const int bh   = blockIdx.x;         // b*NH + h
    const int qt   = blockIdx.y;
    const int b    = bh >> 4, h = bh & 15;

    const int arow = lane & 15;
    const int acol = (lane >> 4) * 4;
    const int brow = ((lane >> 4) << 3) + (lane & 7);
    const int bcol = ((lane >> 3) & 1) * 4;

    const uint32_t Ks_s = (uint32_t)__cvta_generic_to_shared(&Ks[0][0][0]);
    const uint32_t Vt_s = (uint32_t)__cvta_generic_to_shared(&Vt[0][0][0]);
    const uint32_t Ps_s = (uint32_t)__cvta_generic_to_shared(&Ps[0][0]);
    const uint32_t KSTAGE = 32u*68u*4u;
    const uint32_t VSTAGE = 64u*36u*4u;

    // --- Q fragments -> registers (one-time, tf32-rounded) ---
    const float* Qb    = Qh + ((size_t)bh * SEQ + qt*64) * DEPTH;
    const float* qrow0 = Qb + (w*16 + g    ) * DEPTH;
    const float* qrow1 = Qb + (w*16 + g + 8) * DEPTH;
    uint32_t qf[8][4];
#pragma unroll
    for (int kb8 = 0; kb8 < 8; ++kb8) {
        qf[kb8][0] = __float_as_uint(to_tf32(__ldg(qrow0 + kb8*8 + t)));
        qf[kb8][1] = __float_as_uint(to_tf32(__ldg(qrow1 + kb8*8 + t)));
        qf[kb8][2] = __float_as_uint(to_tf32(__ldg(qrow0 + kb8*8 + t + 4)));
        qf[kb8][3] = __float_as_uint(to_tf32(__ldg(qrow1 + kb8*8 + t + 4)));
    }

    const float* Kb0 = Kh  + (size_t)bh * SEQ * DEPTH;
    const float* Vb0 = VhT + (size_t)bh * DEPTH * SEQ;
    const float* Mb  = mask + ((size_t)b * SEQ + qt*64) * SEQ;
    const int pr = w*16 + g;

    // cp.async mappings
    const int krow = tid >> 2, kcb = (tid & 3) * 16;   // K: 32 rows x 64 floats
    const int vrow = tid >> 1, vcb = (tid & 1) * 16;   // V: 64 rows x 32 floats
    const float* Kp = Kb0 + (size_t)krow * DEPTH + kcb;
    const float* Vp = Vb0 + (size_t)vrow * SEQ + vcb;
    const uint32_t Kd = Ks_s + (uint32_t)((krow*68 + kcb) * 4);
    const uint32_t Vd = Vt_s + (uint32_t)((vrow*36 + vcb) * 4);

#define ATTN_ISSUE(st, ktc)                                          \
    do {                                                             \
        const float* kp = Kp + (size_t)(ktc) * 32 * DEPTH;           \
        const float* vp = Vp + (ktc) * 32;                           \
        const uint32_t kd = Kd + (st) * KSTAGE;                      \
        const uint32_t vd = Vd + (st) * VSTAGE;                      \
        cpasync16(kd,      kp);      cpasync16(kd + 16, kp + 4);     \
        cpasync16(kd + 32, kp + 8);  cpasync16(kd + 48, kp + 12);    \
        cpasync16(vd,      vp);      cpasync16(vd + 16, vp + 4);     \
        cpasync16(vd + 32, vp + 8);  cpasync16(vd + 48, vp + 12);    \
        cp_commit();                                                 \
    } while (0)

    ATTN_ISSUE(0, 0);
    ATTN_ISSUE(1, 1);
    cp_wait<1>();
    __syncthreads();

    float oacc[8][4] = {};
    float m0 = -INFINITY, m1 = -INFINITY, l0 = 0.f, l1 = 0.f;

    for (int kt = 0; kt < NT; ++kt) {
        const int cur = kt & 1;
        const uint32_t Ksb = Ks_s + (uint32_t)cur * KSTAGE;
        const uint32_t Vtb = Vt_s + (uint32_t)cur * VSTAGE;

        // S = Q @ K^T  (16x32 per warp)
        float sacc[4][4] = {};
#pragma unroll
        for (int ks = 0; ks < 8; ++ks) {
            const int kb = ks * 8;
            uint32_t bf[4][2];
#pragma unroll
            for (int p = 0; p < 2; ++p) {
                uint32_t r[4];
                ldsm4(r, Ksb + (uint32_t)(((p*16 + brow)*68 + kb + bcol) * 4));
                bf[p*2  ][0] = cvtu(r[0]); bf[p*2  ][1] = cvtu(r[1]);
                bf[p*2+1][0] = cvtu(r[2]); bf[p*2+1][1] = cvtu(r[3]);
            }
#pragma unroll
            for (int nt = 0; nt < 4; ++nt)
                mma8(sacc[nt], qf[ks], bf[nt]);
        }

        // scale + additive mask
#pragma unroll
        for (int nt = 0; nt < 4; ++nt) {
            const int c0 = kt*32 + nt*8 + t*2;
            float2 mlo = *(const float2*)(Mb + (size_t)(w*16 + g    )*SEQ + c0);
            float2 mhi = *(const float2*)(Mb + (size_t)(w*16 + g + 8)*SEQ + c0);
            sacc[nt][0] = fmaf(mlo.x, -1e9f, sacc[nt][0]*0.125f);
            sacc[nt][1] = fmaf(mlo.y, -1e9f, sacc[nt][1]*0.125f);
            sacc[nt][2] = fmaf(mhi.x, -1e9f, sacc[nt][2]*0.125f);
            sacc[nt][3] = fmaf(mhi.y, -1e9f, sacc[nt][3]*0.125f);
        }

        // online softmax (2 rows/thread, quad reduction)
        float rm0 = -INFINITY, rm1 = -INFINITY;
#pragma unroll
        for (int nt = 0; nt < 4; ++nt) {
            rm0 = fmaxf(rm0, fmaxf(sacc[nt][0], sacc[nt][1]));
            rm1 = fmaxf(rm1, fmaxf(sacc[nt][2], sacc[nt][3]));
        }
        rm0 = fmaxf(rm0, __shfl_xor_sync(0xffffffffu, rm0, 1));
        rm0 = fmaxf(rm0, __shfl_xor_sync(0xffffffffu, rm0, 2));
        rm1 = fmaxf(rm1, __shfl_xor_sync(0xffffffffu, rm1, 1));
        rm1 = fmaxf(rm1, __shfl_xor_sync(0xffffffffu, rm1, 2));

        const float mn0 = fmaxf(m0, rm0), mn1 = fmaxf(m1, rm1);
        const float a0  = __expf(m0 - mn0), a1 = __expf(m1 - mn1);
        m0 = mn0; m1 = mn1;

        float sum0 = 0.f, sum1 = 0.f;
#pragma unroll
        for (int nt = 0; nt < 4; ++nt) {
            sacc[nt][0] = __expf(sacc[nt][0] - mn0); sum0 += sacc[nt][0];
            sacc[nt][1] = __expf(sacc[nt][1] - mn0); sum0 += sacc[nt][1];
            sacc[nt][2] = __expf(sacc[nt][2] - mn1); sum1 += sacc[nt][2];
            sacc[nt][3] = __expf(sacc[nt][3] - mn1); sum1 += sacc[nt][3];
        }
        sum0 += __shfl_xor_sync(0xffffffffu, sum0, 1);
        sum0 += __shfl_xor_sync(0xffffffffu, sum0, 2);
        sum1 += __shfl_xor_sync(0xffffffffu, sum1, 1);
        sum1 += __shfl_xor_sync(0xffffffffu, sum1, 2);
        l0 = l0*a0 + sum0;
        l1 = l1*a1 + sum1;
#pragma unroll
        for (int nt = 0; nt < 8; ++nt) {
            oacc[nt][0] *= a0; oacc[nt][1] *= a0;
            oacc[nt][2] *= a1; oacc[nt][3] *= a1;
        }

        // P -> smem (warp-private rows, tf32-rounded)
#pragma unroll
        for (int nt = 0; nt < 4; ++nt) {
            *(float2*)&Ps[pr    ][nt*8 + t*2] = make_float2(to_tf32(sacc[nt][0]), to_tf32(sacc[nt][1]));
            *(float2*)&Ps[pr + 8][nt*8 + t*2] = make_float2(to_tf32(sacc[nt][2]), to_tf32(sacc[nt][3]));
        }
        __syncwarp();

        // O += P @ V   (16x64 per warp, K=32)
#pragma unroll
        for (int ks = 0; ks < 4; ++ks) {
            const int kb = ks * 8;
            uint32_t af[4];
            ldsm4(af, Ps_s + (uint32_t)(((w*16 + arow)*36 + kb + acol) * 4));
            uint32_t bf[8][2];
#pragma unroll
            for (int p = 0; p < 4; ++p) {
                uint32_t r[4];
                ldsm4(r, Vtb + (uint32_t)(((p*16 + brow)*36 + kb + bcol) * 4));
                bf[p*2  ][0] = cvtu(r[0]); bf[p*2  ][1] = cvtu(r[1]);
                bf[p*2+1][0] = cvtu(r[2]); bf[p*2+1][1] = cvtu(r[3]);
            }
#pragma unroll
            for (int nt = 0; nt < 8; ++nt)
                mma8(oacc[nt], af, bf[nt]);
        }

        __syncthreads();            // stage cur fully consumed
        if (kt + 2 < NT) {
            ATTN_ISSUE(cur, kt + 2);
            cp_wait<1>();           // stage for kt+1 complete
        } else {
            cp_wait<0>();
        }
        __syncthreads();
    }
#undef ATTN_ISSUE

    // epilogue: normalize + concat heads -> Oc[b*S + s][h*64 + d]
    const float inv0 = 1.f / l0, inv1 = 1.f / l1;
    const size_t row0 = (size_t)b*SEQ + qt*64 + w*16 + g;
#pragma unroll
    for (int nt = 0; nt < 8; ++nt) {
        const int c = h*64 + nt*8 + t*2;
        *(float2*)(Oc + row0     * DMODEL + c) = make_float2(oacc[nt][0]*inv0, oacc[nt][1]*inv0);
        *(float2*)(Oc + (row0+8) * DMODEL + c) = make_float2(oacc[nt][2]*inv1, oacc[nt][3]*inv1);
    }
}

// ---------------------------------------------------------------------------
extern "C" void kernel_launch(void* const* d_in, const int* in_sizes, int n_in,
                              void* d_out, int out_size)
{
    const float* v    = (const float*)d_in[0];
    const float* k    = (const float*)d_in[1];
    const float* q    = (const float*)d_in[2];
    const float* mask = (const float*)d_in[3];
    const float* wq   = (const float*)d_in[4];
    const float* bq   = (const float*)d_in[5];
    const float* wk   = (const float*)d_in[6];
    const float* bk   = (const float*)d_in[7];
    const float* wv   = (const float*)d_in[8];
    const float* bv   = (const float*)d_in[9];
    const float* wo   = (const float*)d_in[10];
    const float* bo   = (const float*)d_in[11];
    float* out = (float*)d_out;

    float *Qh, *Kh, *VhT, *Oc;
    cudaGetSymbolAddress((void**)&Qh,  g_Qh);
    cudaGetSymbolAddress((void**)&Kh,  g_Kh);
    cudaGetSymbolAddress((void**)&VhT, g_VhT);
    cudaGetSymbolAddress((void**)&Oc,  g_Oc);

    // fused Q/K/V projections: one launch, blockIdx.z selects the GEMM
    dim3 gqkv(DMODEL/128, MROWS/128, 3);  // (8, 32, 3)
    gemm_tc<true, true><<<gqkv, 256>>>(q, wq, bq, Qh,
                                       k, wk, bk, Kh,
                                       v, wv, bv, VhT);

    dim3 ga(BATCH*NH, SEQ/64);            // (32, 32)
    attn_tc<<<ga, 128>>>(Qh, Kh, VhT, mask, Oc);

    dim3 gg(DMODEL/128, MROWS/128);       // (8, 32)
    gemm_tc<false, false><<<gg, 256>>>(Oc, wo, bo, out,
                                       nullptr, nullptr, nullptr, nullptr,
                                       nullptr, nullptr, nullptr, nullptr);
}

// round 15
// speedup vs baseline: 2.1895x; 1.0133x over previous
#include <cuda_runtime.h>
#include <math.h>
#include <stdint.h>

#define DMODEL 1024
#define NH     16
#define DEPTH  64
#define BATCH  2
#define SEQ    2048
#define MROWS  (BATCH*SEQ)   // 4096
#define NT     (SEQ/32)      // 64 kv chunks

// Scratch (allocation-free rule: __device__ globals)
__device__ float g_Qh[BATCH*NH*SEQ*DEPTH];
__device__ float g_Kh[BATCH*NH*SEQ*DEPTH];
__device__ float g_VhT[BATCH*NH*DEPTH*SEQ];   // V stored transposed: [b,h,d,s]
__device__ float g_Oc[MROWS*DMODEL];

__device__ __forceinline__ float to_tf32(float x) {
    float r;
    asm("cvt.rna.tf32.f32 %0, %1;" : "=f"(r) : "f"(x));
    return r;
}
__device__ __forceinline__ uint32_t cvtu(uint32_t u) {
    return __float_as_uint(to_tf32(__uint_as_float(u)));
}

__device__ __forceinline__ void mma8(float c[4], const uint32_t a[4], const uint32_t b[2]) {
    asm volatile(
        "mma.sync.aligned.m16n8k8.row.col.f32.tf32.tf32.f32 "
        "{%0,%1,%2,%3},{%4,%5,%6,%7},{%8,%9},{%0,%1,%2,%3};\n"
        : "+f"(c[0]), "+f"(c[1]), "+f"(c[2]), "+f"(c[3])
        : "r"(a[0]), "r"(a[1]), "r"(a[2]), "r"(a[3]), "r"(b[0]), "r"(b[1]));
}

__device__ __forceinline__ void ldsm4(uint32_t* r, uint32_t addr) {
    asm volatile("ldmatrix.sync.aligned.m8n8.x4.shared.b16 {%0,%1,%2,%3}, [%4];"
                 : "=r"(r[0]), "=r"(r[1]), "=r"(r[2]), "=r"(r[3]) : "r"(addr));
}

__device__ __forceinline__ void cpasync16(uint32_t dst, const void* src) {
    asm volatile("cp.async.ca.shared.global [%0], [%1], 16;\n" :: "r"(dst), "l"(src));
}
__device__ __forceinline__ void cp_commit() {
    asm volatile("cp.async.commit_group;\n");
}
template<int N>
__device__ __forceinline__ void cp_wait() {
    asm volatile("cp.async.wait_group %0;\n" :: "n"(N));
}

// ---------------------------------------------------------------------------
// C = A[4096,1024] @ W[1024,1024]^T + bias, tf32 tensor-core GEMM.
// 128x128 tile, BK=16, cp.async 2-stage double buffer, ldmatrix fragments.
// QKV=true: fused Q/K/V projections via blockIdx.z; z==2 (V) writes output
// transposed per head [b,h,d,s]; all SPLIT outputs stored tf32-ROUNDED so the
// attention kernel needs no cvt (numerically identical: one rna rounding per
// value before MMA use, same as before).
// PRE_A=true: A operand already tf32-rounded in global (skip A-frag cvt).
// ---------------------------------------------------------------------------
template<bool SPLIT, bool QKV, bool PRE_A>
__global__ __launch_bounds__(256)
void gemm_tc(const float* __restrict__ A0, const float* __restrict__ W0,
             const float* __restrict__ b0, float* __restrict__ C0,
             const float* __restrict__ A1, const float* __restrict__ W1,
             const float* __restrict__ b1, float* __restrict__ C1,
             const float* __restrict__ A2, const float* __restrict__ W2,
             const float* __restrict__ b2, float* __restrict__ C2)
{
    __shared__ __align__(16) float As[2][128][20];
    __shared__ __align__(16) float Ws[2][128][20];

    const float* A    = A0;
    const float* W    = W0;
    const float* bias = b0;
    float*       C    = C0;
    if (QKV) {
        const int z = blockIdx.z;
        if (z == 1) { A = A1; W = W1; bias = b1; C = C1; }
        else if (z == 2) { A = A2; W = W2; bias = b2; C = C2; }
    }

    const int tid  = threadIdx.x;
    const int lane = tid & 31, wid = tid >> 5;
    const int wm   = wid >> 2, wn = wid & 3;
    const int g    = lane >> 2, t = lane & 3;
    const int bm   = blockIdx.y * 128, bn = blockIdx.x * 128;

    const int arow = lane & 15;
    const int acol = (lane >> 4) * 4;
    const int brow = ((lane >> 4) << 3) + (lane & 7);
    const int bcol = ((lane >> 3) & 1) * 4;

    const uint32_t As_s = (uint32_t)__cvta_generic_to_shared(&As[0][0][0]);
    const uint32_t Ws_s = (uint32_t)__cvta_generic_to_shared(&Ws[0][0][0]);
    const uint32_t STAGE = 128u * 20u * 4u;

    const int crow = tid >> 2;
    const int csc  = (tid & 3) * 4;
    const float* Arow0 = A + (size_t)(bm + crow     ) * DMODEL + csc;
    const float* Arow1 = A + (size_t)(bm + crow + 64) * DMODEL + csc;
    const float* Wrow0 = W + (size_t)(bn + crow     ) * DMODEL + csc;
    const float* Wrow1 = W + (size_t)(bn + crow + 64) * DMODEL + csc;
    const uint32_t Ad0 = As_s + (uint32_t)((crow      * 20 + csc) * 4);
    const uint32_t Ad1 = As_s + (uint32_t)(((crow+64) * 20 + csc) * 4);
    const uint32_t Wd0 = Ws_s + (uint32_t)((crow      * 20 + csc) * 4);
    const uint32_t Wd1 = Ws_s + (uint32_t)(((crow+64) * 20 + csc) * 4);

#define GEMM_ISSUE(st, k0)                                   \
    do {                                                     \
        const uint32_t so = (st) * STAGE;                    \
        cpasync16(Ad0 + so, Arow0 + (k0));                   \
        cpasync16(Ad1 + so, Arow1 + (k0));                   \
        cpasync16(Wd0 + so, Wrow0 + (k0));                   \
        cpasync16(Wd1 + so, Wrow1 + (k0));                   \
        cp_commit();                                         \
    } while (0)

    GEMM_ISSUE(0, 0);
    GEMM_ISSUE(1, 16);
    cp_wait<1>();
    __syncthreads();

    float acc[4][4][4] = {};
    const int NI = DMODEL / 16;   // 64

    for (int i = 0; i < NI; ++i) {
        const int cur = i & 1;
        const uint32_t Asb = As_s + (uint32_t)cur * STAGE;
        const uint32_t Wsb = Ws_s + (uint32_t)cur * STAGE;

#pragma unroll
        for (int ks = 0; ks < 2; ++ks) {
            const int kb = ks * 8;
            uint32_t af[4][4], bf[4][2];
#pragma unroll
            for (int mt = 0; mt < 4; ++mt) {
                ldsm4(af[mt], Asb + (uint32_t)(((wm*64 + mt*16 + arow)*20 + kb + acol) * 4));
                if (!PRE_A) {
#pragma unroll
                    for (int j = 0; j < 4; ++j) af[mt][j] = cvtu(af[mt][j]);
                }
            }
#pragma unroll
            for (int p = 0; p < 2; ++p) {
                uint32_t r[4];
                ldsm4(r, Wsb + (uint32_t)(((wn*32 + p*16 + brow)*20 + kb + bcol) * 4));
                bf[p*2  ][0] = cvtu(r[0]); bf[p*2  ][1] = cvtu(r[1]);
                bf[p*2+1][0] = cvtu(r[2]); bf[p*2+1][1] = cvtu(r[3]);
            }
#pragma unroll
            for (int mt = 0; mt < 4; ++mt)
#pragma unroll
                for (int nt = 0; nt < 4; ++nt)
                    mma8(acc[mt][nt], af[mt], bf[nt]);
        }

        __syncthreads();
        if (i + 2 < NI) {
            GEMM_ISSUE(cur, (i + 2) * 16);
            cp_wait<1>();
        } else {
            cp_wait<0>();
        }
        __syncthreads();
    }
#undef GEMM_ISSUE

    // epilogue
    const bool vtrans = QKV && (blockIdx.z == 2);
#pragma unroll
    for (int mt = 0; mt < 4; ++mt) {
        const int r0 = bm + wm*64 + mt*16 + g;
#pragma unroll
        for (int nt = 0; nt < 4; ++nt) {
            const int c0 = bn + wn*32 + nt*8 + t*2;
            const float bb0 = bias[c0], bb1 = bias[c0 + 1];
            float v00 = acc[mt][nt][0] + bb0, v01 = acc[mt][nt][1] + bb1;
            float v10 = acc[mt][nt][2] + bb0, v11 = acc[mt][nt][3] + bb1;
            if (SPLIT) {
                // pre-round for the attention kernel (single rna rounding per
                // value before MMA use — identical numerics)
                v00 = to_tf32(v00); v01 = to_tf32(v01);
                v10 = to_tf32(v10); v11 = to_tf32(v11);
                const int bb = r0 >> 11;
                const int s  = r0 & (SEQ - 1);
                const int h  = c0 >> 6;
                const int d  = c0 & 63;
                if (vtrans) {
                    float* base = C + (((size_t)(bb*NH + h))*DEPTH + d)*SEQ + s;
                    base[0]       = v00;  base[SEQ]     = v01;
                    base[8]       = v10;  base[SEQ + 8] = v11;
                } else {
                    float* p0 = C + (((size_t)(bb*NH + h))*SEQ + s    )*DEPTH + d;
                    float* p1 = C + (((size_t)(bb*NH + h))*SEQ + s + 8)*DEPTH + d;
                    *(float2*)p0 = make_float2(v00, v01);
                    *(float2*)p1 = make_float2(v10, v11);
                }
            } else {
                *(float2*)(C + (size_t)r0      * DMODEL + c0) = make_float2(v00, v01);
                *(float2*)(C + (size_t)(r0+8)  * DMODEL + c0) = make_float2(v10, v11);
            }
        }
    }
}

// ---------------------------------------------------------------------------
// Flash attention, tf32 tensor cores, cp.async K/V pipeline.
// Q/K/V arrive PRE-ROUNDED to tf32 from the projection kernel -> zero cvt in
// the hot loop. V pre-transposed globally ([b,h,d,s]). Output Oc written
// tf32-rounded so the out-projection GEMM skips its A-fragment cvts.
// Smem: Ks[2][32][68] + Vt[2][64][36] + Ps[64][36] = 44.0 KB.
// ---------------------------------------------------------------------------
__global__ __launch_bounds__(128, 4)
void attn_tc(const float* __restrict__ Qh, const float* __restrict__ Kh,
             const float* __restrict__ VhT, const float* __restrict__ mask,
             float* __restrict__ Oc)
{
    __shared__ __align__(16) float Ks[2][32][68];
    __shared__ __align__(16) float Vt[2][64][36];
    __shared__ __align__(16) float Ps[64][36];

    const int tid  = threadIdx.x;
    const int lane = tid & 31, w = tid >> 5;
    const int g    = lane >> 2, t = lane & 3;
    const int bh   = blockIdx.x;         // b*NH + h
    const int qt   = blockIdx.y;
    const int b    = bh >> 4, h = bh & 15;

    const int arow = lane & 15;
    const int acol = (lane >> 4) * 4;
    const int brow = ((lane >> 4) << 3) + (lane & 7);
    const int bcol = ((lane >> 3) & 1) * 4;

    const uint32_t Ks_s = (uint32_t)__cvta_generic_to_shared(&Ks[0][0][0]);
    const uint32_t Vt_s = (uint32_t)__cvta_generic_to_shared(&Vt[0][0][0]);
    const uint32_t Ps_s = (uint32_t)__cvta_generic_to_shared(&Ps[0][0]);
    const uint32_t KSTAGE = 32u*68u*4u;
    const uint32_t VSTAGE = 64u*36u*4u;

    // --- Q fragments -> registers (pre-rounded in global; direct load) ---
    const float* Qb    = Qh + ((size_t)bh * SEQ + qt*64) * DEPTH;
    const float* qrow0 = Qb + (w*16 + g    ) * DEPTH;
    const float* qrow1 = Qb + (w*16 + g + 8) * DEPTH;
    uint32_t qf[8][4];
#pragma unroll
    for (int kb8 = 0; kb8 < 8; ++kb8) {
        qf[kb8][0] = __float_as_uint(__ldg(qrow0 + kb8*8 + t));
        qf[kb8][1] = __float_as_uint(__ldg(qrow1 + kb8*8 + t));
        qf[kb8][2] = __float_as_uint(__ldg(qrow0 + kb8*8 + t + 4));
        qf[kb8][3] = __float_as_uint(__ldg(qrow1 + kb8*8 + t + 4));
    }

    const float* Kb0 = Kh  + (size_t)bh * SEQ * DEPTH;
    const float* Vb0 = VhT + (size_t)bh * DEPTH * SEQ;
    const float* Mb  = mask + ((size_t)b * SEQ + qt*64) * SEQ;
    const int pr = w*16 + g;

    // cp.async mappings
    const int krow = tid >> 2, kcb = (tid & 3) * 16;   // K: 32 rows x 64 floats
    const int vrow = tid >> 1, vcb = (tid & 1) * 16;   // V: 64 rows x 32 floats
    const float* Kp = Kb0 + (size_t)krow * DEPTH + kcb;
    const float* Vp = Vb0 + (size_t)vrow * SEQ + vcb;
    const uint32_t Kd = Ks_s + (uint32_t)((krow*68 + kcb) * 4);
    const uint32_t Vd = Vt_s + (uint32_t)((vrow*36 + vcb) * 4);

#define ATTN_ISSUE(st, ktc)                                          \
    do {                                                             \
        const float* kp = Kp + (size_t)(ktc) * 32 * DEPTH;           \
        const float* vp = Vp + (ktc) * 32;                           \
        const uint32_t kd = Kd + (st) * KSTAGE;                      \
        const uint32_t vd = Vd + (st) * VSTAGE;                      \
        cpasync16(kd,      kp);      cpasync16(kd + 16, kp + 4);     \
        cpasync16(kd + 32, kp + 8);  cpasync16(kd + 48, kp + 12);    \
        cpasync16(vd,      vp);      cpasync16(vd + 16, vp + 4);     \
        cpasync16(vd + 32, vp + 8);  cpasync16(vd + 48, vp + 12);    \
        cp_commit();                                                 \
    } while (0)

    ATTN_ISSUE(0, 0);
    ATTN_ISSUE(1, 1);
    cp_wait<1>();
    __syncthreads();

    float oacc[8][4] = {};
    float m0 = -INFINITY, m1 = -INFINITY, l0 = 0.f, l1 = 0.f;

    for (int kt = 0; kt < NT; ++kt) {
        const int cur = kt & 1;
        const uint32_t Ksb = Ks_s + (uint32_t)cur * KSTAGE;
        const uint32_t Vtb = Vt_s + (uint32_t)cur * VSTAGE;

        // S = Q @ K^T  (16x32 per warp)
        float sacc[4][4] = {};
#pragma unroll
        for (int ks = 0; ks < 8; ++ks) {
            const int kb = ks * 8;
            uint32_t bf[4][2];
#pragma unroll
            for (int p = 0; p < 2; ++p) {
                uint32_t r[4];
                ldsm4(r, Ksb + (uint32_t)(((p*16 + brow)*68 + kb + bcol) * 4));
                bf[p*2  ][0] = r[0]; bf[p*2  ][1] = r[1];
                bf[p*2+1][0] = r[2]; bf[p*2+1][1] = r[3];
            }
#pragma unroll
            for (int nt = 0; nt < 4; ++nt)
                mma8(sacc[nt], qf[ks], bf[nt]);
        }

        // scale + additive mask
#pragma unroll
        for (int nt = 0; nt < 4; ++nt) {
            const int c0 = kt*32 + nt*8 + t*2;
            float2 mlo = *(const float2*)(Mb + (size_t)(w*16 + g    )*SEQ + c0);
            float2 mhi = *(const float2*)(Mb + (size_t)(w*16 + g + 8)*SEQ + c0);
            sacc[nt][0] = fmaf(mlo.x, -1e9f, sacc[nt][0]*0.125f);
            sacc[nt][1] = fmaf(mlo.y, -1e9f, sacc[nt][1]*0.125f);
            sacc[nt][2] = fmaf(mhi.x, -1e9f, sacc[nt][2]*0.125f);
            sacc[nt][3] = fmaf(mhi.y, -1e9f, sacc[nt][3]*0.125f);
        }

        // online softmax (2 rows/thread, quad reduction)
        float rm0 = -INFINITY, rm1 = -INFINITY;
#pragma unroll
        for (int nt = 0; nt < 4; ++nt) {
            rm0 = fmaxf(rm0, fmaxf(sacc[nt][0], sacc[nt][1]));
            rm1 = fmaxf(rm1, fmaxf(sacc[nt][2], sacc[nt][3]));
        }
        rm0 = fmaxf(rm0, __shfl_xor_sync(0xffffffffu, rm0, 1));
        rm0 = fmaxf(rm0, __shfl_xor_sync(0xffffffffu, rm0, 2));
        rm1 = fmaxf(rm1, __shfl_xor_sync(0xffffffffu, rm1, 1));
        rm1 = fmaxf(rm1, __shfl_xor_sync(0xffffffffu, rm1, 2));

        const float mn0 = fmaxf(m0, rm0), mn1 = fmaxf(m1, rm1);
        const float a0  = __expf(m0 - mn0), a1 = __expf(m1 - mn1);
        m0 = mn0; m1 = mn1;

        float sum0 = 0.f, sum1 = 0.f;
#pragma unroll
        for (int nt = 0; nt < 4; ++nt) {
            sacc[nt][0] = __expf(sacc[nt][0] - mn0); sum0 += sacc[nt][0];
            sacc[nt][1] = __expf(sacc[nt][1] - mn0); sum0 += sacc[nt][1];
            sacc[nt][2] = __expf(sacc[nt][2] - mn1); sum1 += sacc[nt][2];
            sacc[nt][3] = __expf(sacc[nt][3] - mn1); sum1 += sacc[nt][3];
        }
        sum0 += __shfl_xor_sync(0xffffffffu, sum0, 1);
        sum0 += __shfl_xor_sync(0xffffffffu, sum0, 2);
        sum1 += __shfl_xor_sync(0xffffffffu, sum1, 1);
        sum1 += __shfl_xor_sync(0xffffffffu, sum1, 2);
        l0 = l0*a0 + sum0;
        l1 = l1*a1 + sum1;
#pragma unroll
        for (int nt = 0; nt < 8; ++nt) {
            oacc[nt][0] *= a0; oacc[nt][1] *= a0;
            oacc[nt][2] *= a1; oacc[nt][3] *= a1;
        }

        // P -> smem (warp-private rows, tf32-rounded)
#pragma unroll
        for (int nt = 0; nt < 4; ++nt) {
            *(float2*)&Ps[pr    ][nt*8 + t*2] = make_float2(to_tf32(sacc[nt][0]), to_tf32(sacc[nt][1]));
            *(float2*)&Ps[pr + 8][nt*8 + t*2] = make_float2(to_tf32(sacc[nt][2]), to_tf32(sacc[nt][3]));
        }
        __syncwarp();

        // O += P @ V   (16x64 per warp, K=32)
#pragma unroll
        for (int ks = 0; ks < 4; ++ks) {
            const int kb = ks * 8;
            uint32_t af[4];
            ldsm4(af, Ps_s + (uint32_t)(((w*16 + arow)*36 + kb + acol) * 4));
            uint32_t bf[8][2];
#pragma unroll
            for (int p = 0; p < 4; ++p) {
                uint32_t r[4];
                ldsm4(r, Vtb + (uint32_t)(((p*16 + brow)*36 + kb + bcol) * 4));
                bf[p*2  ][0] = r[0]; bf[p*2  ][1] = r[1];
                bf[p*2+1][0] = r[2]; bf[p*2+1][1] = r[3];
            }
#pragma unroll
            for (int nt = 0; nt < 8; ++nt)
                mma8(oacc[nt], af, bf[nt]);
        }

        __syncthreads();
        if (kt + 2 < NT) {
            ATTN_ISSUE(cur, kt + 2);
            cp_wait<1>();
        } else {
            cp_wait<0>();
        }
        __syncthreads();
    }
#undef ATTN_ISSUE

    // epilogue: normalize + concat heads -> Oc[b*S + s][h*64 + d]
    // stored tf32-rounded so the out-projection skips its A-frag cvts
    const float inv0 = 1.f / l0, inv1 = 1.f / l1;
    const size_t row0 = (size_t)b*SEQ + qt*64 + w*16 + g;
#pragma unroll
    for (int nt = 0; nt < 8; ++nt) {
        const int c = h*64 + nt*8 + t*2;
        *(float2*)(Oc + row0     * DMODEL + c) =
            make_float2(to_tf32(oacc[nt][0]*inv0), to_tf32(oacc[nt][1]*inv0));
        *(float2*)(Oc + (row0+8) * DMODEL + c) =
            make_float2(to_tf32(oacc[nt][2]*inv1), to_tf32(oacc[nt][3]*inv1));
    }
}

// ---------------------------------------------------------------------------
extern "C" void kernel_launch(void* const* d_in, const int* in_sizes, int n_in,
                              void* d_out, int out_size)
{
    const float* v    = (const float*)d_in[0];
    const float* k    = (const float*)d_in[1];
    const float* q    = (const float*)d_in[2];
    const float* mask = (const float*)d_in[3];
    const float* wq   = (const float*)d_in[4];
    const float* bq   = (const float*)d_in[5];
    const float* wk   = (const float*)d_in[6];
    const float* bk   = (const float*)d_in[7];
    const float* wv   = (const float*)d_in[8];
    const float* bv   = (const float*)d_in[9];
    const float* wo   = (const float*)d_in[10];
    const float* bo   = (const float*)d_in[11];
    float* out = (float*)d_out;

    float *Qh, *Kh, *VhT, *Oc;
    cudaGetSymbolAddress((void**)&Qh,  g_Qh);
    cudaGetSymbolAddress((void**)&Kh,  g_Kh);
    cudaGetSymbolAddress((void**)&VhT, g_VhT);
    cudaGetSymbolAddress((void**)&Oc,  g_Oc);

    // fused Q/K/V projections: one launch, blockIdx.z selects the GEMM
    dim3 gqkv(DMODEL/128, MROWS/128, 3);  // (8, 32, 3)
    gemm_tc<true, true, false><<<gqkv, 256>>>(q, wq, bq, Qh,
                                              k, wk, bk, Kh,
                                              v, wv, bv, VhT);

    dim3 ga(BATCH*NH, SEQ/64);            // (32, 32)
    attn_tc<<<ga, 128>>>(Qh, Kh, VhT, mask, Oc);

    dim3 gg(DMODEL/128, MROWS/128);       // (8, 32)
    gemm_tc<false, false, true><<<gg, 256>>>(Oc, wo, bo, out,
                                             nullptr, nullptr, nullptr, nullptr,
                                             nullptr, nullptr, nullptr, nullptr);
}